// round 1
// baseline (speedup 1.0000x reference)
#include <cuda_runtime.h>
#include <math.h>

// Problem constants
#define Bb   2
#define SS   2048
#define DD   2048
#define HH   16
#define HD   128
#define MTOT 4096   // Bb*SS

// Scratch (device globals: allocation-free rule)
__device__ float g_Q[(size_t)Bb * HH * SS * HD];   // [b,h,s,hd]
__device__ float g_K[(size_t)Bb * HH * SS * HD];
__device__ float g_V[(size_t)Bb * HH * SS * HD];
__device__ float g_A[(size_t)MTOT * DD];           // attention out, [b,s,d]

// ---------------------------------------------------------------------------
// GEMM: Y[m,n] = sum_k X[m,k] * W[n,k]   (X:[M,K] row-major, W:[N,K] row-major)
// M=4096 fixed by grid, N=2048, K=2048. 128x128 block tile, BK=16,
// 256 threads, 8x8 per-thread microtile. SMEM tiles stored k-major
// (pitch 132) so the inner loop is 4x LDS.128 per thread per k.
// split==1: scatter into [b,h,s,hd] layout (head split epilogue).
// ---------------------------------------------------------------------------
__global__ __launch_bounds__(256) void gemm_xwt(
    const float* __restrict__ X, const float* __restrict__ W,
    float* __restrict__ Y, int split)
{
    __shared__ float As[16 * 132];   // [k][m]
    __shared__ float Bs[16 * 132];   // [k][n]
    const int K = 2048;

    const int tid = threadIdx.x;
    const int tx = tid & 15;
    const int ty = tid >> 4;
    const int m0 = blockIdx.y * 128;
    const int n0 = blockIdx.x * 128;

    const int lrow = tid >> 2;          // 0..63
    const int lc4  = (tid & 3) << 2;    // 0,4,8,12

    const float* Xp = X + (size_t)(m0 + lrow) * K + lc4;
    const float* Wp = W + (size_t)(n0 + lrow) * K + lc4;

    float acc[8][8];
    #pragma unroll
    for (int i = 0; i < 8; i++)
        #pragma unroll
        for (int j = 0; j < 8; j++) acc[i][j] = 0.f;

    for (int k0 = 0; k0 < K; k0 += 16) {
        float4 a0 = *(const float4*)(Xp + k0);
        float4 a1 = *(const float4*)(Xp + k0 + (size_t)64 * K);
        float4 b0 = *(const float4*)(Wp + k0);
        float4 b1 = *(const float4*)(Wp + k0 + (size_t)64 * K);

        __syncthreads();  // protect previous iteration's reads
        As[(lc4 + 0) * 132 + lrow] = a0.x;
        As[(lc4 + 1) * 132 + lrow] = a0.y;
        As[(lc4 + 2) * 132 + lrow] = a0.z;
        As[(lc4 + 3) * 132 + lrow] = a0.w;
        As[(lc4 + 0) * 132 + lrow + 64] = a1.x;
        As[(lc4 + 1) * 132 + lrow + 64] = a1.y;
        As[(lc4 + 2) * 132 + lrow + 64] = a1.z;
        As[(lc4 + 3) * 132 + lrow + 64] = a1.w;
        Bs[(lc4 + 0) * 132 + lrow] = b0.x;
        Bs[(lc4 + 1) * 132 + lrow] = b0.y;
        Bs[(lc4 + 2) * 132 + lrow] = b0.z;
        Bs[(lc4 + 3) * 132 + lrow] = b0.w;
        Bs[(lc4 + 0) * 132 + lrow + 64] = b1.x;
        Bs[(lc4 + 1) * 132 + lrow + 64] = b1.y;
        Bs[(lc4 + 2) * 132 + lrow + 64] = b1.z;
        Bs[(lc4 + 3) * 132 + lrow + 64] = b1.w;
        __syncthreads();

        #pragma unroll
        for (int k = 0; k < 16; k++) {
            float4 av0 = *(const float4*)&As[k * 132 + ty * 8];
            float4 av1 = *(const float4*)&As[k * 132 + ty * 8 + 4];
            float4 bv0 = *(const float4*)&Bs[k * 132 + tx * 8];
            float4 bv1 = *(const float4*)&Bs[k * 132 + tx * 8 + 4];
            float a[8] = {av0.x, av0.y, av0.z, av0.w, av1.x, av1.y, av1.z, av1.w};
            float b[8] = {bv0.x, bv0.y, bv0.z, bv0.w, bv1.x, bv1.y, bv1.z, bv1.w};
            #pragma unroll
            for (int i = 0; i < 8; i++)
                #pragma unroll
                for (int j = 0; j < 8; j++)
                    acc[i][j] = fmaf(a[i], b[j], acc[i][j]);
        }
    }

    if (split) {
        #pragma unroll
        for (int i = 0; i < 8; i++) {
            int m = m0 + ty * 8 + i;
            int b = m >> 11;          // /SS
            int s = m & 2047;
            #pragma unroll
            for (int j = 0; j < 8; j++) {
                int n = n0 + tx * 8 + j;
                int h = n >> 7;       // /HD
                int hd = n & 127;
                Y[(((size_t)(b * HH + h) * SS) + s) * HD + hd] = acc[i][j];
            }
        }
    } else {
        #pragma unroll
        for (int i = 0; i < 8; i++) {
            size_t base = (size_t)(m0 + ty * 8 + i) * DD + n0 + tx * 8;
            float4 w0 = make_float4(acc[i][0], acc[i][1], acc[i][2], acc[i][3]);
            float4 w1 = make_float4(acc[i][4], acc[i][5], acc[i][6], acc[i][7]);
            *(float4*)&Y[base]     = w0;
            *(float4*)&Y[base + 4] = w1;
        }
    }
}

// ---------------------------------------------------------------------------
// Flash attention (fp32, online softmax).
// Grid: (S/64, B*H). Block 256 threads. BQ=64, BKV=64, HD=128.
// SMEM: Qs [64][128], Ks transposed [128][68], Vs [64][132], Ps [64][65].
// Per-thread: S-tile 4x4 (ty->q, tx->k), O-tile 4x8 (ty->q, tx->hd).
// ---------------------------------------------------------------------------
#define ATT_SMEM_FLOATS (64*128 + 128*68 + 64*132 + 64*65 + 192)
#define ATT_SMEM_BYTES  (ATT_SMEM_FLOATS * 4)

__global__ __launch_bounds__(256) void attn_kernel(
    const float* __restrict__ Q, const float* __restrict__ Kg,
    const float* __restrict__ V, float* __restrict__ O)
{
    extern __shared__ float smf[];
    float* Qs = smf;                    // [64][128]
    float* Ks = Qs + 64 * 128;          // [d=128][kc pitch 68]
    float* Vs = Ks + 128 * 68;          // [64][132]
    float* Ps = Vs + 64 * 132;          // [64][65]
    float* rm = Ps + 64 * 65;           // [64]
    float* rl = rm + 64;                // [64]
    float* rs = rl + 64;                // [64]

    const int tid = threadIdx.x;
    const int tx = tid & 15;
    const int ty = tid >> 4;
    const int q0 = blockIdx.x * 64;
    const int bh = blockIdx.y;

    const float* Qb = Q  + ((size_t)bh * SS + q0) * HD;
    const float* Kb = Kg + (size_t)bh * SS * HD;
    const float* Vb = V  + (size_t)bh * SS * HD;

    for (int f = tid; f < 2048; f += 256) {
        int r = f >> 5;
        int c = (f & 31) << 2;
        *(float4*)&Qs[r * 128 + c] = *(const float4*)&Qb[(size_t)r * HD + c];
    }
    if (tid < 64) { rm[tid] = -1e30f; rl[tid] = 0.f; }

    float o[4][8];
    #pragma unroll
    for (int i = 0; i < 4; i++)
        #pragma unroll
        for (int j = 0; j < 8; j++) o[i][j] = 0.f;

    const float sm_scale = 0.08838834764831843f;  // 1/sqrt(128)

    for (int kv0 = 0; kv0 < SS; kv0 += 64) {
        __syncthreads();  // previous PV reads done before K/V overwrite
        for (int f = tid; f < 2048; f += 256) {
            int r = f >> 5;
            int c = (f & 31) << 2;
            float4 kv = *(const float4*)&Kb[(size_t)(kv0 + r) * HD + c];
            Ks[(c + 0) * 68 + r] = kv.x;
            Ks[(c + 1) * 68 + r] = kv.y;
            Ks[(c + 2) * 68 + r] = kv.z;
            Ks[(c + 3) * 68 + r] = kv.w;
            *(float4*)&Vs[r * 132 + c] = *(const float4*)&Vb[(size_t)(kv0 + r) * HD + c];
        }
        __syncthreads();

        // S = Q K^T
        float s4[4][4];
        #pragma unroll
        for (int i = 0; i < 4; i++)
            #pragma unroll
            for (int j = 0; j < 4; j++) s4[i][j] = 0.f;

        #pragma unroll 8
        for (int d = 0; d < 128; d++) {
            float a0 = Qs[(ty * 4 + 0) * 128 + d];
            float a1 = Qs[(ty * 4 + 1) * 128 + d];
            float a2 = Qs[(ty * 4 + 2) * 128 + d];
            float a3 = Qs[(ty * 4 + 3) * 128 + d];
            float4 bv = *(const float4*)&Ks[d * 68 + tx * 4];
            s4[0][0] = fmaf(a0, bv.x, s4[0][0]); s4[0][1] = fmaf(a0, bv.y, s4[0][1]);
            s4[0][2] = fmaf(a0, bv.z, s4[0][2]); s4[0][3] = fmaf(a0, bv.w, s4[0][3]);
            s4[1][0] = fmaf(a1, bv.x, s4[1][0]); s4[1][1] = fmaf(a1, bv.y, s4[1][1]);
            s4[1][2] = fmaf(a1, bv.z, s4[1][2]); s4[1][3] = fmaf(a1, bv.w, s4[1][3]);
            s4[2][0] = fmaf(a2, bv.x, s4[2][0]); s4[2][1] = fmaf(a2, bv.y, s4[2][1]);
            s4[2][2] = fmaf(a2, bv.z, s4[2][2]); s4[2][3] = fmaf(a2, bv.w, s4[2][3]);
            s4[3][0] = fmaf(a3, bv.x, s4[3][0]); s4[3][1] = fmaf(a3, bv.y, s4[3][1]);
            s4[3][2] = fmaf(a3, bv.z, s4[3][2]); s4[3][3] = fmaf(a3, bv.w, s4[3][3]);
        }
        #pragma unroll
        for (int i = 0; i < 4; i++)
            #pragma unroll
            for (int j = 0; j < 4; j++)
                Ps[(ty * 4 + i) * 65 + tx * 4 + j] = s4[i][j] * sm_scale;
        __syncthreads();

        // Online softmax: 4 threads per row
        {
            int r = tid >> 2;
            int part = tid & 3;
            float* srow = &Ps[r * 65 + part * 16];
            float mo = rm[r];
            float mx = -1e30f;
            #pragma unroll
            for (int c = 0; c < 16; c++) mx = fmaxf(mx, srow[c]);
            mx = fmaxf(mx, __shfl_xor_sync(0xffffffffu, mx, 1));
            mx = fmaxf(mx, __shfl_xor_sync(0xffffffffu, mx, 2));
            float mn = fmaxf(mo, mx);
            float sum = 0.f;
            #pragma unroll
            for (int c = 0; c < 16; c++) {
                float p = __expf(srow[c] - mn);
                srow[c] = p;
                sum += p;
            }
            sum += __shfl_xor_sync(0xffffffffu, sum, 1);
            sum += __shfl_xor_sync(0xffffffffu, sum, 2);
            if (part == 0) {
                float sc = __expf(mo - mn);
                rm[r] = mn;
                rl[r] = rl[r] * sc + sum;
                rs[r] = sc;
            }
        }
        __syncthreads();

        // Rescale accumulators, then O += P V
        #pragma unroll
        for (int i = 0; i < 4; i++) {
            float sc = rs[ty * 4 + i];
            #pragma unroll
            for (int j = 0; j < 8; j++) o[i][j] *= sc;
        }
        #pragma unroll 4
        for (int k = 0; k < 64; k++) {
            float p0 = Ps[(ty * 4 + 0) * 65 + k];
            float p1 = Ps[(ty * 4 + 1) * 65 + k];
            float p2 = Ps[(ty * 4 + 2) * 65 + k];
            float p3 = Ps[(ty * 4 + 3) * 65 + k];
            float4 v0 = *(const float4*)&Vs[k * 132 + tx * 8];
            float4 v1 = *(const float4*)&Vs[k * 132 + tx * 8 + 4];
            float vv[8] = {v0.x, v0.y, v0.z, v0.w, v1.x, v1.y, v1.z, v1.w};
            #pragma unroll
            for (int j = 0; j < 8; j++) {
                o[0][j] = fmaf(p0, vv[j], o[0][j]);
                o[1][j] = fmaf(p1, vv[j], o[1][j]);
                o[2][j] = fmaf(p2, vv[j], o[2][j]);
                o[3][j] = fmaf(p3, vv[j], o[3][j]);
            }
        }
    }

    // Epilogue: divide by l, write [b,s,d]
    const int b = bh >> 4;
    const int h = bh & 15;
    #pragma unroll
    for (int i = 0; i < 4; i++) {
        int s = q0 + ty * 4 + i;
        float inv = 1.0f / rl[ty * 4 + i];
        size_t base = ((size_t)(b * SS + s)) * DD + h * HD + tx * 8;
        float4 w0 = make_float4(o[i][0] * inv, o[i][1] * inv, o[i][2] * inv, o[i][3] * inv);
        float4 w1 = make_float4(o[i][4] * inv, o[i][5] * inv, o[i][6] * inv, o[i][7] * inv);
        *(float4*)&O[base]     = w0;
        *(float4*)&O[base + 4] = w1;
    }
}

// ---------------------------------------------------------------------------
extern "C" void kernel_launch(void* const* d_in, const int* in_sizes, int n_in,
                              void* d_out, int out_size)
{
    const float* x  = (const float*)d_in[0];
    const float* Wq = (const float*)d_in[1];
    const float* Wk = (const float*)d_in[2];
    const float* Wv = (const float*)d_in[3];
    const float* Wo = (const float*)d_in[4];

    float *Q, *K, *V, *A;
    cudaGetSymbolAddress((void**)&Q, g_Q);
    cudaGetSymbolAddress((void**)&K, g_K);
    cudaGetSymbolAddress((void**)&V, g_V);
    cudaGetSymbolAddress((void**)&A, g_A);

    cudaFuncSetAttribute(attn_kernel,
                         cudaFuncAttributeMaxDynamicSharedMemorySize,
                         ATT_SMEM_BYTES);

    dim3 gb(16, 32);   // N/128, M/128
    dim3 tb(256);
    gemm_xwt<<<gb, tb>>>(x, Wq, Q, 1);
    gemm_xwt<<<gb, tb>>>(x, Wk, K, 1);
    gemm_xwt<<<gb, tb>>>(x, Wv, V, 1);
    attn_kernel<<<dim3(SS / 64, Bb * HH), tb, ATT_SMEM_BYTES>>>(Q, K, V, A);
    gemm_xwt<<<gb, tb>>>(A, Wo, (float*)d_out, 0);
}

// round 3
// speedup vs baseline: 1.4430x; 1.4430x over previous
#include <cuda_runtime.h>
#include <cuda_bf16.h>
#include <stdint.h>
#include <math.h>

// Problem constants
#define Bb   2
#define SS   2048
#define DD   2048
#define HH   16
#define HD   128
#define MTOT 4096   // Bb*SS
#define KK   2048

// ---------------------------------------------------------------------------
// Scratch (device globals: allocation-free rule)
// ---------------------------------------------------------------------------
__device__ float g_Q[(size_t)Bb * HH * SS * HD];   // [b,h,s,hd]
__device__ float g_K[(size_t)Bb * HH * SS * HD];
__device__ float g_V[(size_t)Bb * HH * SS * HD];
__device__ float g_A[(size_t)MTOT * DD];           // attention out, [b,s,d]

__device__ __nv_bfloat16 g_xhi[(size_t)MTOT * DD];
__device__ __nv_bfloat16 g_xlo[(size_t)MTOT * DD];
__device__ __nv_bfloat16 g_whi[(size_t)4 * DD * DD];  // Wq,Wk,Wv,Wo
__device__ __nv_bfloat16 g_wlo[(size_t)4 * DD * DD];
__device__ __nv_bfloat16 g_ahi[(size_t)MTOT * DD];
__device__ __nv_bfloat16 g_alo[(size_t)MTOT * DD];

// ---------------------------------------------------------------------------
// PTX helpers (family-safe: sm_80-class instructions only)
// ---------------------------------------------------------------------------
__device__ __forceinline__ uint32_t smem_to_u32(const void* p) {
    uint32_t a;
    asm("{ .reg .u64 t; cvta.to.shared.u64 t, %1; cvt.u32.u64 %0, t; }"
        : "=r"(a) : "l"(p));
    return a;
}

__device__ __forceinline__ void cp_async16(uint32_t saddr, const void* gaddr) {
    asm volatile("cp.async.cg.shared.global [%0], [%1], 16;"
                 :: "r"(saddr), "l"(gaddr) : "memory");
}
#define CP_COMMIT() asm volatile("cp.async.commit_group;" ::: "memory")
#define CP_WAIT1()  asm volatile("cp.async.wait_group 1;" ::: "memory")

#define LDSM4(r0, r1, r2, r3, addr) \
    asm volatile("ldmatrix.sync.aligned.m8n8.x4.shared.b16 {%0,%1,%2,%3}, [%4];" \
                 : "=r"(r0), "=r"(r1), "=r"(r2), "=r"(r3) : "r"(addr))

#define MMA16816(d, a, b) \
    asm volatile("mma.sync.aligned.m16n8k16.row.col.f32.bf16.bf16.f32 " \
                 "{%0,%1,%2,%3}, {%4,%5,%6,%7}, {%8,%9}, {%0,%1,%2,%3};" \
                 : "+f"((d)[0]), "+f"((d)[1]), "+f"((d)[2]), "+f"((d)[3]) \
                 : "r"((a)[0]), "r"((a)[1]), "r"((a)[2]), "r"((a)[3]), \
                   "r"((b)[0]), "r"((b)[1]))

// ---------------------------------------------------------------------------
// Split fp32 -> (hi, lo) bf16 pair.  n4 = element_count / 4.
// ---------------------------------------------------------------------------
__global__ __launch_bounds__(256) void split_bf16_kernel(
    const float* __restrict__ in,
    __nv_bfloat16* __restrict__ hi, __nv_bfloat16* __restrict__ lo, int n4)
{
    int i = blockIdx.x * blockDim.x + threadIdx.x;
    if (i >= n4) return;
    float4 v = ((const float4*)in)[i];
    __nv_bfloat16 h0 = __float2bfloat16(v.x);
    __nv_bfloat16 h1 = __float2bfloat16(v.y);
    __nv_bfloat16 h2 = __float2bfloat16(v.z);
    __nv_bfloat16 h3 = __float2bfloat16(v.w);
    __nv_bfloat16 l0 = __float2bfloat16(v.x - __bfloat162float(h0));
    __nv_bfloat16 l1 = __float2bfloat16(v.y - __bfloat162float(h1));
    __nv_bfloat16 l2 = __float2bfloat16(v.z - __bfloat162float(h2));
    __nv_bfloat16 l3 = __float2bfloat16(v.w - __bfloat162float(h3));
    ((__nv_bfloat162*)hi)[2 * i + 0] = __halves2bfloat162(h0, h1);
    ((__nv_bfloat162*)hi)[2 * i + 1] = __halves2bfloat162(h2, h3);
    ((__nv_bfloat162*)lo)[2 * i + 0] = __halves2bfloat162(l0, l1);
    ((__nv_bfloat162*)lo)[2 * i + 1] = __halves2bfloat162(l2, l3);
}

// ---------------------------------------------------------------------------
// HMMA GEMM:  Y[m,n] = sum_k X[m,k] * W[n,k]  via split-bf16 (3 mma terms).
// CTA tile 128x128, BK=32, 3-stage cp.async pipeline, 8 warps (warp 64x32).
// SMEM tiles: pitch 40 bf16 (80 B) -> conflict-free ldmatrix.
// Stage layout: Ahi | Alo | Bhi | Blo, 10240 B each, stage = 40960 B.
// split==1: scatter into [b,h,s,hd] (BN == HD == 128 -> one head per n-tile).
// ---------------------------------------------------------------------------
#define TPITCHB  80            // bytes per smem row
#define TILEB    10240         // 128 * 80
#define STAGEB   40960
#define NSTAGE   3
#define GSMEM_TOTAL (NSTAGE * STAGEB)
#define NCHUNK   (KK / 32)

__global__ __launch_bounds__(256, 1) void gemm_hmma(
    const __nv_bfloat16* __restrict__ Xhi, const __nv_bfloat16* __restrict__ Xlo,
    const __nv_bfloat16* __restrict__ Whi, const __nv_bfloat16* __restrict__ Wlo,
    float* __restrict__ Y, int split)
{
    extern __shared__ char smem[];
    const uint32_t sb = smem_to_u32(smem);

    const int tid  = threadIdx.x;
    const int wid  = tid >> 5;
    const int lane = tid & 31;
    const int wm   = wid >> 2;    // 0..1  (M warp)
    const int wn   = wid & 3;     // 0..3  (N warp)
    const int m0   = blockIdx.y * 128;
    const int n0   = blockIdx.x * 128;

    // ---- loader mapping: 4 groups of 64 threads, one tile each ----
    const int ltile = tid >> 6;         // 0:Ahi 1:Alo 2:Bhi 3:Blo
    const int lwi   = tid & 63;
    const __nv_bfloat16* gbase =
        (ltile == 0) ? Xhi : (ltile == 1) ? Xlo : (ltile == 2) ? Whi : Wlo;
    const int rowoff = (ltile < 2) ? m0 : n0;
    const uint32_t stile = sb + ltile * TILEB;

    auto load_stage = [&](int chunk, int s) {
        const int k0 = chunk * 32;
        const uint32_t sstage = stile + s * STAGEB;
        #pragma unroll
        for (int i = 0; i < 8; i++) {
            int idx = lwi + i * 64;
            int row = idx >> 2;
            int c   = idx & 3;
            cp_async16(sstage + (uint32_t)(row * TPITCHB + c * 16),
                       gbase + (size_t)(rowoff + row) * KK + k0 + c * 8);
        }
    };

    // ---- fragment address bases (within a stage) ----
    const uint32_t aoff = (uint32_t)((wm * 64 + (lane & 15)) * TPITCHB + (lane >> 4) * 16);
    const uint32_t boff = (uint32_t)((wn * 32 + ((lane >> 4) << 3) + (lane & 7)) * TPITCHB
                                     + ((lane >> 3) & 1) * 16);

    float acc[4][4][4];
    #pragma unroll
    for (int mt = 0; mt < 4; mt++)
        #pragma unroll
        for (int nt = 0; nt < 4; nt++)
            #pragma unroll
            for (int r = 0; r < 4; r++) acc[mt][nt][r] = 0.f;

    load_stage(0, 0); CP_COMMIT();
    load_stage(1, 1); CP_COMMIT();

    for (int t = 0; t < NCHUNK; t++) {
        const int s = t % NSTAGE;
        CP_WAIT1();            // stage t resident
        __syncthreads();       // and everyone done reading stage (t+2)%NSTAGE

        if (t + 2 < NCHUNK) load_stage(t + 2, (t + 2) % NSTAGE);
        CP_COMMIT();

        const uint32_t stA  = sb + s * STAGEB;          // Ahi
        const uint32_t stAl = stA + TILEB;              // Alo
        const uint32_t stB  = stA + 2 * TILEB;          // Bhi
        const uint32_t stBl = stA + 3 * TILEB;          // Blo

        #pragma unroll
        for (int ks = 0; ks < 2; ks++) {
            uint32_t ah[4][4], al[4][4], bh[4][2], bl[4][2];
            #pragma unroll
            for (int mt = 0; mt < 4; mt++) {
                LDSM4(ah[mt][0], ah[mt][1], ah[mt][2], ah[mt][3],
                      stA  + aoff + mt * (16 * TPITCHB) + ks * 32);
                LDSM4(al[mt][0], al[mt][1], al[mt][2], al[mt][3],
                      stAl + aoff + mt * (16 * TPITCHB) + ks * 32);
            }
            #pragma unroll
            for (int bt = 0; bt < 2; bt++) {
                uint32_t r0, r1, r2, r3;
                LDSM4(r0, r1, r2, r3, stB + boff + bt * (16 * TPITCHB) + ks * 32);
                bh[bt * 2][0] = r0; bh[bt * 2][1] = r1;
                bh[bt * 2 + 1][0] = r2; bh[bt * 2 + 1][1] = r3;
                LDSM4(r0, r1, r2, r3, stBl + boff + bt * (16 * TPITCHB) + ks * 32);
                bl[bt * 2][0] = r0; bl[bt * 2][1] = r1;
                bl[bt * 2 + 1][0] = r2; bl[bt * 2 + 1][1] = r3;
            }
            #pragma unroll
            for (int mt = 0; mt < 4; mt++)
                #pragma unroll
                for (int nt = 0; nt < 4; nt++) {
                    MMA16816(acc[mt][nt], ah[mt], bh[nt]);
                    MMA16816(acc[mt][nt], ah[mt], bl[nt]);
                    MMA16816(acc[mt][nt], al[mt], bh[nt]);
                }
        }
        __syncthreads();       // all reads of stage s done before overwrite
    }

    // ---- epilogue: registers -> gmem ----
    #pragma unroll
    for (int mt = 0; mt < 4; mt++) {
        const int mrow = m0 + wm * 64 + mt * 16 + (lane >> 2);
        #pragma unroll
        for (int nt = 0; nt < 4; nt++) {
            const int ncl = wn * 32 + nt * 8 + (lane & 3) * 2;   // col within tile
            float* p0;
            float* p1;
            if (split) {
                const int b = mrow >> 11;
                const int srow = mrow & 2047;
                const int h = n0 >> 7;
                float* basep = Y + (((size_t)(b * HH + h) * SS) + srow) * HD + ncl;
                p0 = basep;
                p1 = basep + (size_t)8 * HD;
            } else {
                float* basep = Y + (size_t)mrow * DD + n0 + ncl;
                p0 = basep;
                p1 = basep + (size_t)8 * DD;
            }
            *(float2*)p0 = make_float2(acc[mt][nt][0], acc[mt][nt][1]);
            *(float2*)p1 = make_float2(acc[mt][nt][2], acc[mt][nt][3]);
        }
    }
}

// ---------------------------------------------------------------------------
// Flash attention (fp32, online softmax) — unchanged.
// ---------------------------------------------------------------------------
#define ATT_SMEM_FLOATS (64*128 + 128*68 + 64*132 + 64*65 + 192)
#define ATT_SMEM_BYTES  (ATT_SMEM_FLOATS * 4)

__global__ __launch_bounds__(256) void attn_kernel(
    const float* __restrict__ Q, const float* __restrict__ Kg,
    const float* __restrict__ V, float* __restrict__ O)
{
    extern __shared__ float smf[];
    float* Qs = smf;
    float* Ks = Qs + 64 * 128;
    float* Vs = Ks + 128 * 68;
    float* Ps = Vs + 64 * 132;
    float* rm = Ps + 64 * 65;
    float* rl = rm + 64;
    float* rs = rl + 64;

    const int tid = threadIdx.x;
    const int tx = tid & 15;
    const int ty = tid >> 4;
    const int q0 = blockIdx.x * 64;
    const int bh = blockIdx.y;

    const float* Qb = Q  + ((size_t)bh * SS + q0) * HD;
    const float* Kb = Kg + (size_t)bh * SS * HD;
    const float* Vb = V  + (size_t)bh * SS * HD;

    for (int f = tid; f < 2048; f += 256) {
        int r = f >> 5;
        int c = (f & 31) << 2;
        *(float4*)&Qs[r * 128 + c] = *(const float4*)&Qb[(size_t)r * HD + c];
    }
    if (tid < 64) { rm[tid] = -1e30f; rl[tid] = 0.f; }

    float o[4][8];
    #pragma unroll
    for (int i = 0; i < 4; i++)
        #pragma unroll
        for (int j = 0; j < 8; j++) o[i][j] = 0.f;

    const float sm_scale = 0.08838834764831843f;

    for (int kv0 = 0; kv0 < SS; kv0 += 64) {
        __syncthreads();
        for (int f = tid; f < 2048; f += 256) {
            int r = f >> 5;
            int c = (f & 31) << 2;
            float4 kv = *(const float4*)&Kb[(size_t)(kv0 + r) * HD + c];
            Ks[(c + 0) * 68 + r] = kv.x;
            Ks[(c + 1) * 68 + r] = kv.y;
            Ks[(c + 2) * 68 + r] = kv.z;
            Ks[(c + 3) * 68 + r] = kv.w;
            *(float4*)&Vs[r * 132 + c] = *(const float4*)&Vb[(size_t)(kv0 + r) * HD + c];
        }
        __syncthreads();

        float s4[4][4];
        #pragma unroll
        for (int i = 0; i < 4; i++)
            #pragma unroll
            for (int j = 0; j < 4; j++) s4[i][j] = 0.f;

        #pragma unroll 8
        for (int d = 0; d < 128; d++) {
            float a0 = Qs[(ty * 4 + 0) * 128 + d];
            float a1 = Qs[(ty * 4 + 1) * 128 + d];
            float a2 = Qs[(ty * 4 + 2) * 128 + d];
            float a3 = Qs[(ty * 4 + 3) * 128 + d];
            float4 bv = *(const float4*)&Ks[d * 68 + tx * 4];
            s4[0][0] = fmaf(a0, bv.x, s4[0][0]); s4[0][1] = fmaf(a0, bv.y, s4[0][1]);
            s4[0][2] = fmaf(a0, bv.z, s4[0][2]); s4[0][3] = fmaf(a0, bv.w, s4[0][3]);
            s4[1][0] = fmaf(a1, bv.x, s4[1][0]); s4[1][1] = fmaf(a1, bv.y, s4[1][1]);
            s4[1][2] = fmaf(a1, bv.z, s4[1][2]); s4[1][3] = fmaf(a1, bv.w, s4[1][3]);
            s4[2][0] = fmaf(a2, bv.x, s4[2][0]); s4[2][1] = fmaf(a2, bv.y, s4[2][1]);
            s4[2][2] = fmaf(a2, bv.z, s4[2][2]); s4[2][3] = fmaf(a2, bv.w, s4[2][3]);
            s4[3][0] = fmaf(a3, bv.x, s4[3][0]); s4[3][1] = fmaf(a3, bv.y, s4[3][1]);
            s4[3][2] = fmaf(a3, bv.z, s4[3][2]); s4[3][3] = fmaf(a3, bv.w, s4[3][3]);
        }
        #pragma unroll
        for (int i = 0; i < 4; i++)
            #pragma unroll
            for (int j = 0; j < 4; j++)
                Ps[(ty * 4 + i) * 65 + tx * 4 + j] = s4[i][j] * sm_scale;
        __syncthreads();

        {
            int r = tid >> 2;
            int part = tid & 3;
            float* srow = &Ps[r * 65 + part * 16];
            float mo = rm[r];
            float mx = -1e30f;
            #pragma unroll
            for (int c = 0; c < 16; c++) mx = fmaxf(mx, srow[c]);
            mx = fmaxf(mx, __shfl_xor_sync(0xffffffffu, mx, 1));
            mx = fmaxf(mx, __shfl_xor_sync(0xffffffffu, mx, 2));
            float mn = fmaxf(mo, mx);
            float sum = 0.f;
            #pragma unroll
            for (int c = 0; c < 16; c++) {
                float p = __expf(srow[c] - mn);
                srow[c] = p;
                sum += p;
            }
            sum += __shfl_xor_sync(0xffffffffu, sum, 1);
            sum += __shfl_xor_sync(0xffffffffu, sum, 2);
            if (part == 0) {
                float sc = __expf(mo - mn);
                rm[r] = mn;
                rl[r] = rl[r] * sc + sum;
                rs[r] = sc;
            }
        }
        __syncthreads();

        #pragma unroll
        for (int i = 0; i < 4; i++) {
            float sc = rs[ty * 4 + i];
            #pragma unroll
            for (int j = 0; j < 8; j++) o[i][j] *= sc;
        }
        #pragma unroll 4
        for (int k = 0; k < 64; k++) {
            float p0 = Ps[(ty * 4 + 0) * 65 + k];
            float p1 = Ps[(ty * 4 + 1) * 65 + k];
            float p2 = Ps[(ty * 4 + 2) * 65 + k];
            float p3 = Ps[(ty * 4 + 3) * 65 + k];
            float4 v0 = *(const float4*)&Vs[k * 132 + tx * 8];
            float4 v1 = *(const float4*)&Vs[k * 132 + tx * 8 + 4];
            float vv[8] = {v0.x, v0.y, v0.z, v0.w, v1.x, v1.y, v1.z, v1.w};
            #pragma unroll
            for (int j = 0; j < 8; j++) {
                o[0][j] = fmaf(p0, vv[j], o[0][j]);
                o[1][j] = fmaf(p1, vv[j], o[1][j]);
                o[2][j] = fmaf(p2, vv[j], o[2][j]);
                o[3][j] = fmaf(p3, vv[j], o[3][j]);
            }
        }
    }

    const int b = bh >> 4;
    const int h = bh & 15;
    #pragma unroll
    for (int i = 0; i < 4; i++) {
        int s = q0 + ty * 4 + i;
        float inv = 1.0f / rl[ty * 4 + i];
        size_t base = ((size_t)(b * SS + s)) * DD + h * HD + tx * 8;
        float4 w0 = make_float4(o[i][0] * inv, o[i][1] * inv, o[i][2] * inv, o[i][3] * inv);
        float4 w1 = make_float4(o[i][4] * inv, o[i][5] * inv, o[i][6] * inv, o[i][7] * inv);
        *(float4*)&O[base]     = w0;
        *(float4*)&O[base + 4] = w1;
    }
}

// ---------------------------------------------------------------------------
extern "C" void kernel_launch(void* const* d_in, const int* in_sizes, int n_in,
                              void* d_out, int out_size)
{
    const float* x  = (const float*)d_in[0];
    const float* Wq = (const float*)d_in[1];
    const float* Wk = (const float*)d_in[2];
    const float* Wv = (const float*)d_in[3];
    const float* Wo = (const float*)d_in[4];

    float *Q, *K, *V, *A;
    __nv_bfloat16 *xhi, *xlo, *whi, *wlo, *ahi, *alo;
    cudaGetSymbolAddress((void**)&Q, g_Q);
    cudaGetSymbolAddress((void**)&K, g_K);
    cudaGetSymbolAddress((void**)&V, g_V);
    cudaGetSymbolAddress((void**)&A, g_A);
    cudaGetSymbolAddress((void**)&xhi, g_xhi);
    cudaGetSymbolAddress((void**)&xlo, g_xlo);
    cudaGetSymbolAddress((void**)&whi, g_whi);
    cudaGetSymbolAddress((void**)&wlo, g_wlo);
    cudaGetSymbolAddress((void**)&ahi, g_ahi);
    cudaGetSymbolAddress((void**)&alo, g_alo);

    cudaFuncSetAttribute(attn_kernel, cudaFuncAttributeMaxDynamicSharedMemorySize,
                         ATT_SMEM_BYTES);
    cudaFuncSetAttribute(gemm_hmma, cudaFuncAttributeMaxDynamicSharedMemorySize,
                         GSMEM_TOTAL);

    const size_t WSZ = (size_t)DD * DD;
    const int xn4 = (int)((size_t)MTOT * DD / 4);
    const int wn4 = (int)(WSZ / 4);

    split_bf16_kernel<<<(xn4 + 255) / 256, 256>>>(x, xhi, xlo, xn4);
    split_bf16_kernel<<<(wn4 + 255) / 256, 256>>>(Wq, whi + 0 * WSZ, wlo + 0 * WSZ, wn4);
    split_bf16_kernel<<<(wn4 + 255) / 256, 256>>>(Wk, whi + 1 * WSZ, wlo + 1 * WSZ, wn4);
    split_bf16_kernel<<<(wn4 + 255) / 256, 256>>>(Wv, whi + 2 * WSZ, wlo + 2 * WSZ, wn4);
    split_bf16_kernel<<<(wn4 + 255) / 256, 256>>>(Wo, whi + 3 * WSZ, wlo + 3 * WSZ, wn4);

    dim3 gg(DD / 128, MTOT / 128);   // (N tiles, M tiles)
    gemm_hmma<<<gg, 256, GSMEM_TOTAL>>>(xhi, xlo, whi + 0 * WSZ, wlo + 0 * WSZ, Q, 1);
    gemm_hmma<<<gg, 256, GSMEM_TOTAL>>>(xhi, xlo, whi + 1 * WSZ, wlo + 1 * WSZ, K, 1);
    gemm_hmma<<<gg, 256, GSMEM_TOTAL>>>(xhi, xlo, whi + 2 * WSZ, wlo + 2 * WSZ, V, 1);

    attn_kernel<<<dim3(SS / 64, Bb * HH), 256, ATT_SMEM_BYTES>>>(Q, K, V, A);

    split_bf16_kernel<<<(xn4 + 255) / 256, 256>>>(A, ahi, alo, xn4);
    gemm_hmma<<<gg, 256, GSMEM_TOTAL>>>(ahi, alo, whi + 3 * WSZ, wlo + 3 * WSZ,
                                        (float*)d_out, 0);
}

// round 4
// speedup vs baseline: 2.8791x; 1.9952x over previous
#include <cuda_runtime.h>
#include <cuda_bf16.h>
#include <stdint.h>
#include <math.h>

// Problem constants
#define Bb   2
#define SS   2048
#define DD   2048
#define HH   16
#define HD   128
#define MTOT 4096   // Bb*SS
#define KK   2048

// ---------------------------------------------------------------------------
// Scratch (device globals: allocation-free rule)
// ---------------------------------------------------------------------------
__device__ __nv_bfloat16 g_xhi[(size_t)MTOT * DD];
__device__ __nv_bfloat16 g_xlo[(size_t)MTOT * DD];
__device__ __nv_bfloat16 g_whi[(size_t)4 * DD * DD];  // Wq,Wk,Wv,Wo
__device__ __nv_bfloat16 g_wlo[(size_t)4 * DD * DD];
__device__ __nv_bfloat16 g_qhi[(size_t)Bb * HH * SS * HD];  // [b,h,s,hd]
__device__ __nv_bfloat16 g_qlo[(size_t)Bb * HH * SS * HD];
__device__ __nv_bfloat16 g_khi[(size_t)Bb * HH * SS * HD];
__device__ __nv_bfloat16 g_klo[(size_t)Bb * HH * SS * HD];
__device__ __nv_bfloat16 g_vhi[(size_t)Bb * HH * SS * HD];
__device__ __nv_bfloat16 g_vlo[(size_t)Bb * HH * SS * HD];
__device__ __nv_bfloat16 g_ahi[(size_t)MTOT * DD];          // attn out [b,s,d]
__device__ __nv_bfloat16 g_alo[(size_t)MTOT * DD];

// ---------------------------------------------------------------------------
// PTX helpers (family-safe: sm_80-class instructions only)
// ---------------------------------------------------------------------------
__device__ __forceinline__ uint32_t smem_to_u32(const void* p) {
    uint32_t a;
    asm("{ .reg .u64 t; cvta.to.shared.u64 t, %1; cvt.u32.u64 %0, t; }"
        : "=r"(a) : "l"(p));
    return a;
}

__device__ __forceinline__ void cp_async16(uint32_t saddr, const void* gaddr) {
    asm volatile("cp.async.cg.shared.global [%0], [%1], 16;"
                 :: "r"(saddr), "l"(gaddr) : "memory");
}
#define CP_COMMIT() asm volatile("cp.async.commit_group;" ::: "memory")
#define CP_WAIT1()  asm volatile("cp.async.wait_group 1;" ::: "memory")

#define LDSM4(r0, r1, r2, r3, addr) \
    asm volatile("ldmatrix.sync.aligned.m8n8.x4.shared.b16 {%0,%1,%2,%3}, [%4];" \
                 : "=r"(r0), "=r"(r1), "=r"(r2), "=r"(r3) : "r"(addr))

#define LDSM4T(r0, r1, r2, r3, addr) \
    asm volatile("ldmatrix.sync.aligned.m8n8.x4.trans.shared.b16 {%0,%1,%2,%3}, [%4];" \
                 : "=r"(r0), "=r"(r1), "=r"(r2), "=r"(r3) : "r"(addr))

#define MMA16816(d, a, b) \
    asm volatile("mma.sync.aligned.m16n8k16.row.col.f32.bf16.bf16.f32 " \
                 "{%0,%1,%2,%3}, {%4,%5,%6,%7}, {%8,%9}, {%0,%1,%2,%3};" \
                 : "+f"((d)[0]), "+f"((d)[1]), "+f"((d)[2]), "+f"((d)[3]) \
                 : "r"((a)[0]), "r"((a)[1]), "r"((a)[2]), "r"((a)[3]), \
                   "r"((b)[0]), "r"((b)[1]))

__device__ __forceinline__ uint32_t packbf(float x, float y) {
    __nv_bfloat162 t = __floats2bfloat162_rn(x, y);
    return *(uint32_t*)&t;
}

// ---------------------------------------------------------------------------
// Split fp32 -> (hi, lo) bf16 pair.  n4 = element_count / 4.
// ---------------------------------------------------------------------------
__global__ __launch_bounds__(256) void split_bf16_kernel(
    const float* __restrict__ in,
    __nv_bfloat16* __restrict__ hi, __nv_bfloat16* __restrict__ lo, int n4)
{
    int i = blockIdx.x * blockDim.x + threadIdx.x;
    if (i >= n4) return;
    float4 v = ((const float4*)in)[i];
    __nv_bfloat16 h0 = __float2bfloat16(v.x);
    __nv_bfloat16 h1 = __float2bfloat16(v.y);
    __nv_bfloat16 h2 = __float2bfloat16(v.z);
    __nv_bfloat16 h3 = __float2bfloat16(v.w);
    __nv_bfloat16 l0 = __float2bfloat16(v.x - __bfloat162float(h0));
    __nv_bfloat16 l1 = __float2bfloat16(v.y - __bfloat162float(h1));
    __nv_bfloat16 l2 = __float2bfloat16(v.z - __bfloat162float(h2));
    __nv_bfloat16 l3 = __float2bfloat16(v.w - __bfloat162float(h3));
    ((__nv_bfloat162*)hi)[2 * i + 0] = __halves2bfloat162(h0, h1);
    ((__nv_bfloat162*)hi)[2 * i + 1] = __halves2bfloat162(h2, h3);
    ((__nv_bfloat162*)lo)[2 * i + 0] = __halves2bfloat162(l0, l1);
    ((__nv_bfloat162*)lo)[2 * i + 1] = __halves2bfloat162(l2, l3);
}

// ---------------------------------------------------------------------------
// HMMA GEMM:  Y[m,n] = sum_k X[m,k] * W[n,k]  via split-bf16 (3 mma terms).
// split==1: writes bf16 hi/lo to Yhi/Ylo in [b,h,s,hd]; split==0: fp32 Yf.
// ---------------------------------------------------------------------------
#define TPITCHB  80            // bytes per smem row
#define TILEB    10240         // 128 * 80
#define STAGEB   40960
#define NSTAGE   3
#define GSMEM_TOTAL (NSTAGE * STAGEB)
#define NCHUNK   (KK / 32)

__global__ __launch_bounds__(256, 1) void gemm_hmma(
    const __nv_bfloat16* __restrict__ Xhi, const __nv_bfloat16* __restrict__ Xlo,
    const __nv_bfloat16* __restrict__ Whi, const __nv_bfloat16* __restrict__ Wlo,
    float* __restrict__ Yf,
    __nv_bfloat16* __restrict__ Yhi, __nv_bfloat16* __restrict__ Ylo, int split)
{
    extern __shared__ char smem[];
    const uint32_t sb = smem_to_u32(smem);

    const int tid  = threadIdx.x;
    const int wid  = tid >> 5;
    const int lane = tid & 31;
    const int wm   = wid >> 2;    // 0..1
    const int wn   = wid & 3;     // 0..3
    const int m0   = blockIdx.y * 128;
    const int n0   = blockIdx.x * 128;

    const int ltile = tid >> 6;         // 0:Ahi 1:Alo 2:Bhi 3:Blo
    const int lwi   = tid & 63;
    const __nv_bfloat16* gbase =
        (ltile == 0) ? Xhi : (ltile == 1) ? Xlo : (ltile == 2) ? Whi : Wlo;
    const int rowoff = (ltile < 2) ? m0 : n0;
    const uint32_t stile = sb + ltile * TILEB;

    auto load_stage = [&](int chunk, int s) {
        const int k0 = chunk * 32;
        const uint32_t sstage = stile + s * STAGEB;
        #pragma unroll
        for (int i = 0; i < 8; i++) {
            int idx = lwi + i * 64;
            int row = idx >> 2;
            int c   = idx & 3;
            cp_async16(sstage + (uint32_t)(row * TPITCHB + c * 16),
                       gbase + (size_t)(rowoff + row) * KK + k0 + c * 8);
        }
    };

    const uint32_t aoff = (uint32_t)((wm * 64 + (lane & 15)) * TPITCHB + (lane >> 4) * 16);
    const uint32_t boff = (uint32_t)((wn * 32 + ((lane >> 4) << 3) + (lane & 7)) * TPITCHB
                                     + ((lane >> 3) & 1) * 16);

    float acc[4][4][4];
    #pragma unroll
    for (int mt = 0; mt < 4; mt++)
        #pragma unroll
        for (int nt = 0; nt < 4; nt++)
            #pragma unroll
            for (int r = 0; r < 4; r++) acc[mt][nt][r] = 0.f;

    load_stage(0, 0); CP_COMMIT();
    load_stage(1, 1); CP_COMMIT();

    for (int t = 0; t < NCHUNK; t++) {
        const int s = t % NSTAGE;
        CP_WAIT1();
        __syncthreads();

        if (t + 2 < NCHUNK) load_stage(t + 2, (t + 2) % NSTAGE);
        CP_COMMIT();

        const uint32_t stA  = sb + s * STAGEB;
        const uint32_t stAl = stA + TILEB;
        const uint32_t stB  = stA + 2 * TILEB;
        const uint32_t stBl = stA + 3 * TILEB;

        #pragma unroll
        for (int ks = 0; ks < 2; ks++) {
            uint32_t ah[4][4], al[4][4], bh[4][2], bl[4][2];
            #pragma unroll
            for (int mt = 0; mt < 4; mt++) {
                LDSM4(ah[mt][0], ah[mt][1], ah[mt][2], ah[mt][3],
                      stA  + aoff + mt * (16 * TPITCHB) + ks * 32);
                LDSM4(al[mt][0], al[mt][1], al[mt][2], al[mt][3],
                      stAl + aoff + mt * (16 * TPITCHB) + ks * 32);
            }
            #pragma unroll
            for (int bt = 0; bt < 2; bt++) {
                uint32_t r0, r1, r2, r3;
                LDSM4(r0, r1, r2, r3, stB + boff + bt * (16 * TPITCHB) + ks * 32);
                bh[bt * 2][0] = r0; bh[bt * 2][1] = r1;
                bh[bt * 2 + 1][0] = r2; bh[bt * 2 + 1][1] = r3;
                LDSM4(r0, r1, r2, r3, stBl + boff + bt * (16 * TPITCHB) + ks * 32);
                bl[bt * 2][0] = r0; bl[bt * 2][1] = r1;
                bl[bt * 2 + 1][0] = r2; bl[bt * 2 + 1][1] = r3;
            }
            #pragma unroll
            for (int mt = 0; mt < 4; mt++)
                #pragma unroll
                for (int nt = 0; nt < 4; nt++) {
                    MMA16816(acc[mt][nt], ah[mt], bh[nt]);
                    MMA16816(acc[mt][nt], ah[mt], bl[nt]);
                    MMA16816(acc[mt][nt], al[mt], bh[nt]);
                }
        }
        __syncthreads();
    }

    // ---- epilogue ----
    #pragma unroll
    for (int mt = 0; mt < 4; mt++) {
        const int mrow = m0 + wm * 64 + mt * 16 + (lane >> 2);
        #pragma unroll
        for (int nt = 0; nt < 4; nt++) {
            const int ncl = wn * 32 + nt * 8 + (lane & 3) * 2;
            if (split) {
                const int b = mrow >> 11;
                const int srow = mrow & 2047;
                const int h = n0 >> 7;
                size_t idx0 = (((size_t)(b * HH + h) * SS) + srow) * HD + ncl;
                size_t idx1 = idx0 + (size_t)8 * HD;
                float a0 = acc[mt][nt][0], a1 = acc[mt][nt][1];
                float a2 = acc[mt][nt][2], a3 = acc[mt][nt][3];
                __nv_bfloat16 h0 = __float2bfloat16(a0), h1 = __float2bfloat16(a1);
                __nv_bfloat16 h2 = __float2bfloat16(a2), h3 = __float2bfloat16(a3);
                *(uint32_t*)(Yhi + idx0) = packbf(a0, a1);
                *(uint32_t*)(Yhi + idx1) = packbf(a2, a3);
                *(uint32_t*)(Ylo + idx0) =
                    packbf(a0 - __bfloat162float(h0), a1 - __bfloat162float(h1));
                *(uint32_t*)(Ylo + idx1) =
                    packbf(a2 - __bfloat162float(h2), a3 - __bfloat162float(h3));
            } else {
                float* basep = Yf + (size_t)mrow * DD + n0 + ncl;
                *(float2*)basep = make_float2(acc[mt][nt][0], acc[mt][nt][1]);
                *(float2*)(basep + (size_t)8 * DD) = make_float2(acc[mt][nt][2], acc[mt][nt][3]);
            }
        }
    }
}

// ---------------------------------------------------------------------------
// HMMA flash attention, split-bf16 (3 terms) for QK^T and PV.
// BQ=64, BKV=64, HD=128.  8 warps: wm=wid>>1 (q rows 16), wn=wid&1.
//   S phase: wn halves kv (32 each).  PV phase: wn halves hd (64 each).
// SMEM: Qhi|Qlo (pitch 272), 2-stage {Khi|Klo|Vhi|Vlo} (pitch 272),
//       Phi|Plo (pitch 144), rowmax[2][64], rowsum[2][64].
// Output written directly as bf16 hi/lo [b,s,d].
// ---------------------------------------------------------------------------
#define APITCH   272
#define PPITCH   144
#define AQTILE   (64 * APITCH)      // 17408
#define AKV_STAGE (4 * AQTILE)      // 69632
#define AOFF_Q    0
#define AOFF_STAGE (2 * AQTILE)
#define AOFF_P    (AOFF_STAGE + 2 * AKV_STAGE)
#define AOFF_PLO  (AOFF_P + 64 * PPITCH)
#define AOFF_STAT (AOFF_PLO + 64 * PPITCH)
#define ATT_SMEM  (AOFF_STAT + 1024)
#define NKV       (SS / 64)

__global__ __launch_bounds__(256, 1) void attn_hmma(
    const __nv_bfloat16* __restrict__ Qhi_g, const __nv_bfloat16* __restrict__ Qlo_g,
    const __nv_bfloat16* __restrict__ Khi_g, const __nv_bfloat16* __restrict__ Klo_g,
    const __nv_bfloat16* __restrict__ Vhi_g, const __nv_bfloat16* __restrict__ Vlo_g,
    __nv_bfloat16* __restrict__ Ahi, __nv_bfloat16* __restrict__ Alo)
{
    extern __shared__ char smem[];
    const uint32_t sb = smem_to_u32(smem);
    float* rowmax = (float*)(smem + AOFF_STAT);          // [2][64]
    float* rowsum = rowmax + 128;                        // [2][64]

    const int tid  = threadIdx.x;
    const int wid  = tid >> 5;
    const int lane = tid & 31;
    const int wm   = wid >> 1;   // 0..3
    const int wn   = wid & 1;    // 0..1
    const int q0   = blockIdx.x * 64;
    const int bh   = blockIdx.y;
    const size_t bhoff = (size_t)bh * SS * HD;

    // ---- load Q (hi,lo) ----
    {
        const __nv_bfloat16* qh = Qhi_g + bhoff + (size_t)q0 * HD;
        const __nv_bfloat16* ql = Qlo_g + bhoff + (size_t)q0 * HD;
        for (int i = tid; i < 64 * 16; i += 256) {
            int r = i >> 4, c = i & 15;
            *(uint4*)(smem + AOFF_Q + r * APITCH + c * 16) =
                *(const uint4*)(qh + (size_t)r * HD + c * 8);
            *(uint4*)(smem + AOFF_Q + AQTILE + r * APITCH + c * 16) =
                *(const uint4*)(ql + (size_t)r * HD + c * 8);
        }
    }

    // ---- KV loader (cp.async, tiles: khi,klo,vhi,vlo) ----
    const __nv_bfloat16* kvbase[4] = {Khi_g + bhoff, Klo_g + bhoff,
                                      Vhi_g + bhoff, Vlo_g + bhoff};
    auto load_kv = [&](int chunk, int s) {
        const uint32_t sstage = sb + AOFF_STAGE + s * AKV_STAGE;
        #pragma unroll
        for (int t = 0; t < 16; t++) {
            int tile = t >> 2;
            int r = (16 * t + (tid >> 4)) & 63;
            int c = tid & 15;
            cp_async16(sstage + tile * AQTILE + r * APITCH + c * 16,
                       kvbase[tile] + (size_t)(chunk * 64 + r) * HD + c * 8);
        }
    };

    // ---- per-thread fragment bases ----
    const uint32_t qBaseHi = sb + AOFF_Q + (wm * 16 + (lane & 15)) * APITCH + (lane >> 4) * 16;
    const uint32_t kFragOff = (uint32_t)((wn * 32 + ((lane >> 4) << 3) + (lane & 7)) * APITCH
                                         + ((lane >> 3) & 1) * 16);
    const uint32_t pBaseHi = sb + AOFF_P + (wm * 16 + (lane & 15)) * PPITCH + (lane >> 4) * 16;
    const int vRow = ((lane >> 3) & 1) * 8 + (lane & 7);
    const uint32_t vCol = (uint32_t)(wn * 128 + (lane >> 4) * 16);

    const int rl0 = wm * 16 + (lane >> 2);   // CTA-local row (and rl0+8)

    float of[8][4];
    #pragma unroll
    for (int i = 0; i < 8; i++)
        #pragma unroll
        for (int j = 0; j < 4; j++) of[i][j] = 0.f;
    float m0 = -1e30f, m1 = -1e30f, l0 = 0.f, l1 = 0.f;

    const float sm_scale = 0.08838834764831843f;  // 1/sqrt(128)

    load_kv(0, 0); CP_COMMIT();
    load_kv(1, 1); CP_COMMIT();

    for (int t = 0; t < NKV; t++) {
        const int s = t & 1;
        CP_WAIT1();
        __syncthreads();   // stage t visible; P/rowsum of t-1 fully consumed

        const uint32_t sK  = sb + AOFF_STAGE + s * AKV_STAGE;
        const uint32_t sKl = sK + AQTILE;
        const uint32_t sV  = sK + 2 * AQTILE;
        const uint32_t sVl = sK + 3 * AQTILE;

        // ---- S = Q K^T ----
        float sf[4][4];
        #pragma unroll
        for (int nt = 0; nt < 4; nt++)
            #pragma unroll
            for (int j = 0; j < 4; j++) sf[nt][j] = 0.f;

        #pragma unroll
        for (int ks = 0; ks < 8; ks++) {
            uint32_t qh[4], ql[4], kh[4][2], kl[4][2];
            LDSM4(qh[0], qh[1], qh[2], qh[3], qBaseHi + ks * 32);
            LDSM4(ql[0], ql[1], ql[2], ql[3], qBaseHi + AQTILE + ks * 32);
            #pragma unroll
            for (int bt = 0; bt < 2; bt++) {
                uint32_t r0, r1, r2, r3;
                LDSM4(r0, r1, r2, r3, sK + kFragOff + bt * (16 * APITCH) + ks * 32);
                kh[bt * 2][0] = r0; kh[bt * 2][1] = r1;
                kh[bt * 2 + 1][0] = r2; kh[bt * 2 + 1][1] = r3;
                LDSM4(r0, r1, r2, r3, sKl + kFragOff + bt * (16 * APITCH) + ks * 32);
                kl[bt * 2][0] = r0; kl[bt * 2][1] = r1;
                kl[bt * 2 + 1][0] = r2; kl[bt * 2 + 1][1] = r3;
            }
            #pragma unroll
            for (int nt = 0; nt < 4; nt++) {
                MMA16816(sf[nt], qh, kh[nt]);
                MMA16816(sf[nt], qh, kl[nt]);
                MMA16816(sf[nt], ql, kh[nt]);
            }
        }

        // ---- online softmax ----
        #pragma unroll
        for (int nt = 0; nt < 4; nt++)
            #pragma unroll
            for (int j = 0; j < 4; j++) sf[nt][j] *= sm_scale;

        float mx0 = -1e30f, mx1 = -1e30f;
        #pragma unroll
        for (int nt = 0; nt < 4; nt++) {
            mx0 = fmaxf(mx0, fmaxf(sf[nt][0], sf[nt][1]));
            mx1 = fmaxf(mx1, fmaxf(sf[nt][2], sf[nt][3]));
        }
        mx0 = fmaxf(mx0, __shfl_xor_sync(0xffffffffu, mx0, 1));
        mx0 = fmaxf(mx0, __shfl_xor_sync(0xffffffffu, mx0, 2));
        mx1 = fmaxf(mx1, __shfl_xor_sync(0xffffffffu, mx1, 1));
        mx1 = fmaxf(mx1, __shfl_xor_sync(0xffffffffu, mx1, 2));
        if ((lane & 3) == 0) {
            rowmax[wn * 64 + rl0]     = mx0;
            rowmax[wn * 64 + rl0 + 8] = mx1;
        }
        __syncthreads();

        const float mn0 = fmaxf(m0, fmaxf(rowmax[rl0], rowmax[64 + rl0]));
        const float mn1 = fmaxf(m1, fmaxf(rowmax[rl0 + 8], rowmax[64 + rl0 + 8]));
        const float al0 = __expf(m0 - mn0);
        const float al1 = __expf(m1 - mn1);

        float sum0 = 0.f, sum1 = 0.f;
        #pragma unroll
        for (int nt = 0; nt < 4; nt++) {
            float p00 = __expf(sf[nt][0] - mn0);
            float p01 = __expf(sf[nt][1] - mn0);
            float p10 = __expf(sf[nt][2] - mn1);
            float p11 = __expf(sf[nt][3] - mn1);
            sum0 += p00 + p01;
            sum1 += p10 + p11;
            const uint32_t coff = (uint32_t)(wn * 64 + nt * 16 + (lane & 3) * 4);
            uint32_t pr = sb + AOFF_P + rl0 * PPITCH + coff;
            __nv_bfloat16 h00 = __float2bfloat16(p00), h01 = __float2bfloat16(p01);
            __nv_bfloat16 h10 = __float2bfloat16(p10), h11 = __float2bfloat16(p11);
            *(uint32_t*)(size_t)0;  // (placeholder removed by compiler? no) 
        }
        // NOTE: the loop above must also store; do it in a second pass to keep
        // register pressure low is worse — restructure: (kept single pass below)
        sum0 = 0.f; sum1 = 0.f;
        #pragma unroll
        for (int nt = 0; nt < 4; nt++) {
            float p00 = __expf(sf[nt][0] - mn0);
            float p01 = __expf(sf[nt][1] - mn0);
            float p10 = __expf(sf[nt][2] - mn1);
            float p11 = __expf(sf[nt][3] - mn1);
            sum0 += p00 + p01;
            sum1 += p10 + p11;
            const uint32_t coff = (uint32_t)(wn * 64 + nt * 16 + (lane & 3) * 4);
            __nv_bfloat16 h00 = __float2bfloat16(p00), h01 = __float2bfloat16(p01);
            __nv_bfloat16 h10 = __float2bfloat16(p10), h11 = __float2bfloat16(p11);
            *(uint32_t*)(smem + AOFF_P + rl0 * PPITCH + coff) = packbf(p00, p01);
            *(uint32_t*)(smem + AOFF_P + (rl0 + 8) * PPITCH + coff) = packbf(p10, p11);
            *(uint32_t*)(smem + AOFF_PLO + rl0 * PPITCH + coff) =
                packbf(p00 - __bfloat162float(h00), p01 - __bfloat162float(h01));
            *(uint32_t*)(smem + AOFF_PLO + (rl0 + 8) * PPITCH + coff) =
                packbf(p10 - __bfloat162float(h10), p11 - __bfloat162float(h11));
        }
        sum0 += __shfl_xor_sync(0xffffffffu, sum0, 1);
        sum0 += __shfl_xor_sync(0xffffffffu, sum0, 2);
        sum1 += __shfl_xor_sync(0xffffffffu, sum1, 1);
        sum1 += __shfl_xor_sync(0xffffffffu, sum1, 2);
        if ((lane & 3) == 0) {
            rowsum[wn * 64 + rl0]     = sum0;
            rowsum[wn * 64 + rl0 + 8] = sum1;
        }
        __syncthreads();

        l0 = l0 * al0 + rowsum[rl0] + rowsum[64 + rl0];
        l1 = l1 * al1 + rowsum[rl0 + 8] + rowsum[64 + rl0 + 8];
        m0 = mn0; m1 = mn1;

        #pragma unroll
        for (int nt = 0; nt < 8; nt++) {
            of[nt][0] *= al0; of[nt][1] *= al0;
            of[nt][2] *= al1; of[nt][3] *= al1;
        }

        // ---- O += P V ----
        #pragma unroll
        for (int ks = 0; ks < 4; ks++) {
            uint32_t ph[4], pl[4];
            LDSM4(ph[0], ph[1], ph[2], ph[3], pBaseHi + ks * 32);
            LDSM4(pl[0], pl[1], pl[2], pl[3], pBaseHi + (64 * PPITCH) + ks * 32);
            const uint32_t vro = (uint32_t)((ks * 16 + vRow) * APITCH) + vCol;
            #pragma unroll
            for (int nt2 = 0; nt2 < 4; nt2++) {
                uint32_t r0, r1, r2, r3;
                uint32_t vh0[2], vh1[2], vl0[2], vl1[2];
                LDSM4T(r0, r1, r2, r3, sV + vro + nt2 * 32);
                vh0[0] = r0; vh0[1] = r1; vh1[0] = r2; vh1[1] = r3;
                LDSM4T(r0, r1, r2, r3, sVl + vro + nt2 * 32);
                vl0[0] = r0; vl0[1] = r1; vl1[0] = r2; vl1[1] = r3;
                MMA16816(of[nt2 * 2], ph, vh0);
                MMA16816(of[nt2 * 2], pl, vh0);
                MMA16816(of[nt2 * 2], ph, vl0);
                MMA16816(of[nt2 * 2 + 1], ph, vh1);
                MMA16816(of[nt2 * 2 + 1], pl, vh1);
                MMA16816(of[nt2 * 2 + 1], ph, vl1);
            }
        }

        __syncthreads();   // all reads of stage s / P done before reuse
        if (t + 2 < NKV) { load_kv(t + 2, s); CP_COMMIT(); }
    }

    // ---- epilogue: O/l -> bf16 hi/lo at [b, s, d] ----
    const int b = bh >> 4;
    const int h = bh & 15;
    const float inv0 = 1.0f / l0;
    const float inv1 = 1.0f / l1;
    const int s0 = q0 + rl0;
    #pragma unroll
    for (int nt = 0; nt < 8; nt++) {
        const int d = h * 128 + wn * 64 + nt * 8 + (lane & 3) * 2;
        size_t idx0 = ((size_t)(b * SS + s0)) * DD + d;
        size_t idx1 = idx0 + (size_t)8 * DD;
        float a0 = of[nt][0] * inv0, a1 = of[nt][1] * inv0;
        float a2 = of[nt][2] * inv1, a3 = of[nt][3] * inv1;
        __nv_bfloat16 h0 = __float2bfloat16(a0), h1 = __float2bfloat16(a1);
        __nv_bfloat16 h2 = __float2bfloat16(a2), h3 = __float2bfloat16(a3);
        *(uint32_t*)(Ahi + idx0) = packbf(a0, a1);
        *(uint32_t*)(Ahi + idx1) = packbf(a2, a3);
        *(uint32_t*)(Alo + idx0) = packbf(a0 - __bfloat162float(h0), a1 - __bfloat162float(h1));
        *(uint32_t*)(Alo + idx1) = packbf(a2 - __bfloat162float(h2), a3 - __bfloat162float(h3));
    }
}

// ---------------------------------------------------------------------------
extern "C" void kernel_launch(void* const* d_in, const int* in_sizes, int n_in,
                              void* d_out, int out_size)
{
    const float* x  = (const float*)d_in[0];
    const float* Wq = (const float*)d_in[1];
    const float* Wk = (const float*)d_in[2];
    const float* Wv = (const float*)d_in[3];
    const float* Wo = (const float*)d_in[4];

    __nv_bfloat16 *xhi, *xlo, *whi, *wlo;
    __nv_bfloat16 *qhi, *qlo, *khi, *klo, *vhi, *vlo, *ahi, *alo;
    cudaGetSymbolAddress((void**)&xhi, g_xhi);
    cudaGetSymbolAddress((void**)&xlo, g_xlo);
    cudaGetSymbolAddress((void**)&whi, g_whi);
    cudaGetSymbolAddress((void**)&wlo, g_wlo);
    cudaGetSymbolAddress((void**)&qhi, g_qhi);
    cudaGetSymbolAddress((void**)&qlo, g_qlo);
    cudaGetSymbolAddress((void**)&khi, g_khi);
    cudaGetSymbolAddress((void**)&klo, g_klo);
    cudaGetSymbolAddress((void**)&vhi, g_vhi);
    cudaGetSymbolAddress((void**)&vlo, g_vlo);
    cudaGetSymbolAddress((void**)&ahi, g_ahi);
    cudaGetSymbolAddress((void**)&alo, g_alo);

    cudaFuncSetAttribute(gemm_hmma, cudaFuncAttributeMaxDynamicSharedMemorySize,
                         GSMEM_TOTAL);
    cudaFuncSetAttribute(attn_hmma, cudaFuncAttributeMaxDynamicSharedMemorySize,
                         ATT_SMEM);

    const size_t WSZ = (size_t)DD * DD;
    const int xn4 = (int)((size_t)MTOT * DD / 4);
    const int wn4 = (int)(WSZ / 4);

    split_bf16_kernel<<<(xn4 + 255) / 256, 256>>>(x, xhi, xlo, xn4);
    split_bf16_kernel<<<(wn4 + 255) / 256, 256>>>(Wq, whi + 0 * WSZ, wlo + 0 * WSZ, wn4);
    split_bf16_kernel<<<(wn4 + 255) / 256, 256>>>(Wk, whi + 1 * WSZ, wlo + 1 * WSZ, wn4);
    split_bf16_kernel<<<(wn4 + 255) / 256, 256>>>(Wv, whi + 2 * WSZ, wlo + 2 * WSZ, wn4);
    split_bf16_kernel<<<(wn4 + 255) / 256, 256>>>(Wo, whi + 3 * WSZ, wlo + 3 * WSZ, wn4);

    dim3 gg(DD / 128, MTOT / 128);
    gemm_hmma<<<gg, 256, GSMEM_TOTAL>>>(xhi, xlo, whi + 0 * WSZ, wlo + 0 * WSZ,
                                        nullptr, qhi, qlo, 1);
    gemm_hmma<<<gg, 256, GSMEM_TOTAL>>>(xhi, xlo, whi + 1 * WSZ, wlo + 1 * WSZ,
                                        nullptr, khi, klo, 1);
    gemm_hmma<<<gg, 256, GSMEM_TOTAL>>>(xhi, xlo, whi + 2 * WSZ, wlo + 2 * WSZ,
                                        nullptr, vhi, vlo, 1);

    attn_hmma<<<dim3(SS / 64, Bb * HH), 256, ATT_SMEM>>>(
        qhi, qlo, khi, klo, vhi, vlo, ahi, alo);

    gemm_hmma<<<gg, 256, GSMEM_TOTAL>>>(ahi, alo, whi + 3 * WSZ, wlo + 3 * WSZ,
                                        (float*)d_out, nullptr, nullptr, 0);
}

// round 5
// speedup vs baseline: 3.0470x; 1.0583x over previous
#include <cuda_runtime.h>
#include <cuda_bf16.h>
#include <stdint.h>
#include <math.h>

// Problem constants
#define Bb   2
#define SS   2048
#define DD   2048
#define HH   16
#define HD   128
#define MTOT 4096   // Bb*SS
#define KK   2048

// ---------------------------------------------------------------------------
// Scratch (device globals: allocation-free rule)
// ---------------------------------------------------------------------------
__device__ __nv_bfloat16 g_xhi[(size_t)MTOT * DD];
__device__ __nv_bfloat16 g_xlo[(size_t)MTOT * DD];
__device__ __nv_bfloat16 g_whi[(size_t)4 * DD * DD];  // Wq,Wk,Wv,Wo
__device__ __nv_bfloat16 g_wlo[(size_t)4 * DD * DD];
__device__ __nv_bfloat16 g_qhi[(size_t)Bb * HH * SS * HD];  // [b,h,s,hd]
__device__ __nv_bfloat16 g_qlo[(size_t)Bb * HH * SS * HD];
__device__ __nv_bfloat16 g_khi[(size_t)Bb * HH * SS * HD];
__device__ __nv_bfloat16 g_klo[(size_t)Bb * HH * SS * HD];
__device__ __nv_bfloat16 g_vhi[(size_t)Bb * HH * SS * HD];
__device__ __nv_bfloat16 g_vlo[(size_t)Bb * HH * SS * HD];
__device__ __nv_bfloat16 g_ahi[(size_t)MTOT * DD];          // attn out [b,s,d]
__device__ __nv_bfloat16 g_alo[(size_t)MTOT * DD];

// ---------------------------------------------------------------------------
// PTX helpers (family-safe: sm_80-class instructions only)
// ---------------------------------------------------------------------------
__device__ __forceinline__ uint32_t smem_to_u32(const void* p) {
    uint32_t a;
    asm("{ .reg .u64 t; cvta.to.shared.u64 t, %1; cvt.u32.u64 %0, t; }"
        : "=r"(a) : "l"(p));
    return a;
}

__device__ __forceinline__ void cp_async16(uint32_t saddr, const void* gaddr) {
    asm volatile("cp.async.cg.shared.global [%0], [%1], 16;"
                 :: "r"(saddr), "l"(gaddr) : "memory");
}
#define CP_COMMIT() asm volatile("cp.async.commit_group;" ::: "memory")
#define CP_WAIT1()  asm volatile("cp.async.wait_group 1;" ::: "memory")
#define CP_WAIT2()  asm volatile("cp.async.wait_group 2;" ::: "memory")

#define LDSM4(r0, r1, r2, r3, addr) \
    asm volatile("ldmatrix.sync.aligned.m8n8.x4.shared.b16 {%0,%1,%2,%3}, [%4];" \
                 : "=r"(r0), "=r"(r1), "=r"(r2), "=r"(r3) : "r"(addr))

#define LDSM4T(r0, r1, r2, r3, addr) \
    asm volatile("ldmatrix.sync.aligned.m8n8.x4.trans.shared.b16 {%0,%1,%2,%3}, [%4];" \
                 : "=r"(r0), "=r"(r1), "=r"(r2), "=r"(r3) : "r"(addr))

#define MMA16816(d, a, b) \
    asm volatile("mma.sync.aligned.m16n8k16.row.col.f32.bf16.bf16.f32 " \
                 "{%0,%1,%2,%3}, {%4,%5,%6,%7}, {%8,%9}, {%0,%1,%2,%3};" \
                 : "+f"((d)[0]), "+f"((d)[1]), "+f"((d)[2]), "+f"((d)[3]) \
                 : "r"((a)[0]), "r"((a)[1]), "r"((a)[2]), "r"((a)[3]), \
                   "r"((b)[0]), "r"((b)[1]))

__device__ __forceinline__ uint32_t packbf(float x, float y) {
    __nv_bfloat162 t = __floats2bfloat162_rn(x, y);
    return *(uint32_t*)&t;
}

// ---------------------------------------------------------------------------
// Fused split: one launch handles x and all 4 weights.
// blockIdx.y: 0 -> x (xn4 quads), 1..4 -> W[y-1] (wn4 quads each).
// ---------------------------------------------------------------------------
__global__ __launch_bounds__(256) void split_all_kernel(
    const float* __restrict__ x,  const float* __restrict__ Wq,
    const float* __restrict__ Wk, const float* __restrict__ Wv,
    const float* __restrict__ Wo,
    __nv_bfloat16* __restrict__ xhi, __nv_bfloat16* __restrict__ xlo,
    __nv_bfloat16* __restrict__ whi, __nv_bfloat16* __restrict__ wlo,
    int xn4, int wn4)
{
    const int y = blockIdx.y;
    const float* in;
    __nv_bfloat16 *hi, *lo;
    int n4;
    if (y == 0) { in = x; hi = xhi; lo = xlo; n4 = xn4; }
    else {
        const float* ws[4] = {Wq, Wk, Wv, Wo};
        in = ws[y - 1];
        const size_t off = (size_t)(y - 1) * DD * DD;
        hi = whi + off; lo = wlo + off; n4 = wn4;
    }
    int i = blockIdx.x * blockDim.x + threadIdx.x;
    if (i >= n4) return;
    float4 v = ((const float4*)in)[i];
    __nv_bfloat16 h0 = __float2bfloat16(v.x);
    __nv_bfloat16 h1 = __float2bfloat16(v.y);
    __nv_bfloat16 h2 = __float2bfloat16(v.z);
    __nv_bfloat16 h3 = __float2bfloat16(v.w);
    ((__nv_bfloat162*)hi)[2 * i + 0] = __halves2bfloat162(h0, h1);
    ((__nv_bfloat162*)hi)[2 * i + 1] = __halves2bfloat162(h2, h3);
    ((__nv_bfloat162*)lo)[2 * i + 0] = __halves2bfloat162(
        __float2bfloat16(v.x - __bfloat162float(h0)),
        __float2bfloat16(v.y - __bfloat162float(h1)));
    ((__nv_bfloat162*)lo)[2 * i + 1] = __halves2bfloat162(
        __float2bfloat16(v.z - __bfloat162float(h2)),
        __float2bfloat16(v.w - __bfloat162float(h3)));
}

// ---------------------------------------------------------------------------
// HMMA GEMM:  Y[m,n] = sum_k X[m,k] * W[n,k]  via split-bf16 (3 mma terms).
// 4-stage cp.async pipeline, ONE __syncthreads per K-chunk.
// qkv==1: gridDim.z selects weight slice + output (Q/K/V), bf16 hi/lo out.
// qkv==0: single weight, fp32 output Yf.
// ---------------------------------------------------------------------------
#define TPITCHB  80            // bytes per smem row
#define TILEB    10240         // 128 * 80
#define STAGEB   40960
#define NSTAGE   4
#define GSMEM_TOTAL (NSTAGE * STAGEB)
#define NCHUNK   (KK / 32)

__global__ __launch_bounds__(256, 1) void gemm_hmma(
    const __nv_bfloat16* __restrict__ Xhi, const __nv_bfloat16* __restrict__ Xlo,
    const __nv_bfloat16* __restrict__ WhiBase, const __nv_bfloat16* __restrict__ WloBase,
    float* __restrict__ Yf,
    __nv_bfloat16* __restrict__ Y0hi, __nv_bfloat16* __restrict__ Y0lo,
    __nv_bfloat16* __restrict__ Y1hi, __nv_bfloat16* __restrict__ Y1lo,
    __nv_bfloat16* __restrict__ Y2hi, __nv_bfloat16* __restrict__ Y2lo,
    int qkv)
{
    extern __shared__ char smem[];
    const uint32_t sb = smem_to_u32(smem);

    const int tid  = threadIdx.x;
    const int wid  = tid >> 5;
    const int lane = tid & 31;
    const int wm   = wid >> 2;    // 0..1
    const int wn   = wid & 3;     // 0..3
    const int m0   = blockIdx.y * 128;
    const int n0   = blockIdx.x * 128;
    const int z    = blockIdx.z;

    const __nv_bfloat16* Whi = WhiBase + (size_t)z * DD * DD;
    const __nv_bfloat16* Wlo = WloBase + (size_t)z * DD * DD;

    const int ltile = tid >> 6;         // 0:Ahi 1:Alo 2:Bhi 3:Blo
    const int lwi   = tid & 63;
    const __nv_bfloat16* gbase =
        (ltile == 0) ? Xhi : (ltile == 1) ? Xlo : (ltile == 2) ? Whi : Wlo;
    const int rowoff = (ltile < 2) ? m0 : n0;
    const uint32_t stile = sb + ltile * TILEB;

    auto load_stage = [&](int chunk, int s) {
        const int k0 = chunk * 32;
        const uint32_t sstage = stile + s * STAGEB;
        #pragma unroll
        for (int i = 0; i < 8; i++) {
            int idx = lwi + i * 64;
            int row = idx >> 2;
            int c   = idx & 3;
            cp_async16(sstage + (uint32_t)(row * TPITCHB + c * 16),
                       gbase + (size_t)(rowoff + row) * KK + k0 + c * 8);
        }
    };

    const uint32_t aoff = (uint32_t)((wm * 64 + (lane & 15)) * TPITCHB + (lane >> 4) * 16);
    const uint32_t boff = (uint32_t)((wn * 32 + ((lane >> 4) << 3) + (lane & 7)) * TPITCHB
                                     + ((lane >> 3) & 1) * 16);

    float acc[4][4][4];
    #pragma unroll
    for (int mt = 0; mt < 4; mt++)
        #pragma unroll
        for (int nt = 0; nt < 4; nt++)
            #pragma unroll
            for (int r = 0; r < 4; r++) acc[mt][nt][r] = 0.f;

    load_stage(0, 0); CP_COMMIT();
    load_stage(1, 1); CP_COMMIT();
    load_stage(2, 2); CP_COMMIT();

    for (int t = 0; t < NCHUNK; t++) {
        const int s = t & 3;
        CP_WAIT2();            // stage t resident (2 newest groups may be pending)
        __syncthreads();       // arrival visible to all; prior reads of slot (t+3)&3 done

        if (t + 3 < NCHUNK) load_stage(t + 3, (t + 3) & 3);
        CP_COMMIT();

        const uint32_t stA  = sb + s * STAGEB;
        const uint32_t stAl = stA + TILEB;
        const uint32_t stB  = stA + 2 * TILEB;
        const uint32_t stBl = stA + 3 * TILEB;

        #pragma unroll
        for (int ks = 0; ks < 2; ks++) {
            uint32_t ah[4][4], al[4][4], bh[4][2], bl[4][2];
            #pragma unroll
            for (int mt = 0; mt < 4; mt++) {
                LDSM4(ah[mt][0], ah[mt][1], ah[mt][2], ah[mt][3],
                      stA  + aoff + mt * (16 * TPITCHB) + ks * 32);
                LDSM4(al[mt][0], al[mt][1], al[mt][2], al[mt][3],
                      stAl + aoff + mt * (16 * TPITCHB) + ks * 32);
            }
            #pragma unroll
            for (int bt = 0; bt < 2; bt++) {
                uint32_t r0, r1, r2, r3;
                LDSM4(r0, r1, r2, r3, stB + boff + bt * (16 * TPITCHB) + ks * 32);
                bh[bt * 2][0] = r0; bh[bt * 2][1] = r1;
                bh[bt * 2 + 1][0] = r2; bh[bt * 2 + 1][1] = r3;
                LDSM4(r0, r1, r2, r3, stBl + boff + bt * (16 * TPITCHB) + ks * 32);
                bl[bt * 2][0] = r0; bl[bt * 2][1] = r1;
                bl[bt * 2 + 1][0] = r2; bl[bt * 2 + 1][1] = r3;
            }
            #pragma unroll
            for (int mt = 0; mt < 4; mt++)
                #pragma unroll
                for (int nt = 0; nt < 4; nt++) {
                    MMA16816(acc[mt][nt], ah[mt], bh[nt]);
                    MMA16816(acc[mt][nt], ah[mt], bl[nt]);
                    MMA16816(acc[mt][nt], al[mt], bh[nt]);
                }
        }
    }

    // ---- epilogue ----
    __nv_bfloat16* Yhi = (z == 0) ? Y0hi : (z == 1) ? Y1hi : Y2hi;
    __nv_bfloat16* Ylo = (z == 0) ? Y0lo : (z == 1) ? Y1lo : Y2lo;
    #pragma unroll
    for (int mt = 0; mt < 4; mt++) {
        const int mrow = m0 + wm * 64 + mt * 16 + (lane >> 2);
        #pragma unroll
        for (int nt = 0; nt < 4; nt++) {
            const int ncl = wn * 32 + nt * 8 + (lane & 3) * 2;
            if (qkv) {
                const int b = mrow >> 11;
                const int srow = mrow & 2047;
                const int h = n0 >> 7;
                size_t idx0 = (((size_t)(b * HH + h) * SS) + srow) * HD + ncl;
                size_t idx1 = idx0 + (size_t)8 * HD;
                float a0 = acc[mt][nt][0], a1 = acc[mt][nt][1];
                float a2 = acc[mt][nt][2], a3 = acc[mt][nt][3];
                __nv_bfloat16 h0 = __float2bfloat16(a0), h1 = __float2bfloat16(a1);
                __nv_bfloat16 h2 = __float2bfloat16(a2), h3 = __float2bfloat16(a3);
                *(uint32_t*)(Yhi + idx0) = packbf(a0, a1);
                *(uint32_t*)(Yhi + idx1) = packbf(a2, a3);
                *(uint32_t*)(Ylo + idx0) =
                    packbf(a0 - __bfloat162float(h0), a1 - __bfloat162float(h1));
                *(uint32_t*)(Ylo + idx1) =
                    packbf(a2 - __bfloat162float(h2), a3 - __bfloat162float(h3));
            } else {
                float* basep = Yf + (size_t)mrow * DD + n0 + ncl;
                *(float2*)basep = make_float2(acc[mt][nt][0], acc[mt][nt][1]);
                *(float2*)(basep + (size_t)8 * DD) = make_float2(acc[mt][nt][2], acc[mt][nt][3]);
            }
        }
    }
}

// ---------------------------------------------------------------------------
// HMMA flash attention, split-bf16 (3 terms) for QK^T and PV.
// BQ=64, BKV=64, HD=128.  8 warps: wm=wid>>1 (q rows 16), wn=wid&1.
// ---------------------------------------------------------------------------
#define APITCH   272
#define PPITCH   144
#define AQTILE   (64 * APITCH)      // 17408
#define AKV_STAGE (4 * AQTILE)      // 69632
#define AOFF_Q    0
#define AOFF_STAGE (2 * AQTILE)
#define AOFF_P    (AOFF_STAGE + 2 * AKV_STAGE)
#define AOFF_PLO  (AOFF_P + 64 * PPITCH)
#define AOFF_STAT (AOFF_PLO + 64 * PPITCH)
#define ATT_SMEM  (AOFF_STAT + 1024)
#define NKV       (SS / 64)

__global__ __launch_bounds__(256, 1) void attn_hmma(
    const __nv_bfloat16* __restrict__ Qhi_g, const __nv_bfloat16* __restrict__ Qlo_g,
    const __nv_bfloat16* __restrict__ Khi_g, const __nv_bfloat16* __restrict__ Klo_g,
    const __nv_bfloat16* __restrict__ Vhi_g, const __nv_bfloat16* __restrict__ Vlo_g,
    __nv_bfloat16* __restrict__ Ahi, __nv_bfloat16* __restrict__ Alo)
{
    extern __shared__ char smem[];
    const uint32_t sb = smem_to_u32(smem);
    float* rowmax = (float*)(smem + AOFF_STAT);          // [2][64]
    float* rowsum = rowmax + 128;                        // [2][64]

    const int tid  = threadIdx.x;
    const int wid  = tid >> 5;
    const int lane = tid & 31;
    const int wm   = wid >> 1;   // 0..3
    const int wn   = wid & 1;    // 0..1
    const int q0   = blockIdx.x * 64;
    const int bh   = blockIdx.y;
    const size_t bhoff = (size_t)bh * SS * HD;

    // ---- load Q (hi,lo) ----
    {
        const __nv_bfloat16* qh = Qhi_g + bhoff + (size_t)q0 * HD;
        const __nv_bfloat16* ql = Qlo_g + bhoff + (size_t)q0 * HD;
        for (int i = tid; i < 64 * 16; i += 256) {
            int r = i >> 4, c = i & 15;
            *(uint4*)(smem + AOFF_Q + r * APITCH + c * 16) =
                *(const uint4*)(qh + (size_t)r * HD + c * 8);
            *(uint4*)(smem + AOFF_Q + AQTILE + r * APITCH + c * 16) =
                *(const uint4*)(ql + (size_t)r * HD + c * 8);
        }
    }

    const __nv_bfloat16* kvbase[4] = {Khi_g + bhoff, Klo_g + bhoff,
                                      Vhi_g + bhoff, Vlo_g + bhoff};
    auto load_kv = [&](int chunk, int s) {
        const uint32_t sstage = sb + AOFF_STAGE + s * AKV_STAGE;
        #pragma unroll
        for (int t = 0; t < 16; t++) {
            int tile = t >> 2;
            int r = (16 * t + (tid >> 4)) & 63;
            int c = tid & 15;
            cp_async16(sstage + tile * AQTILE + r * APITCH + c * 16,
                       kvbase[tile] + (size_t)(chunk * 64 + r) * HD + c * 8);
        }
    };

    const uint32_t qBaseHi = sb + AOFF_Q + (wm * 16 + (lane & 15)) * APITCH + (lane >> 4) * 16;
    const uint32_t kFragOff = (uint32_t)((wn * 32 + ((lane >> 4) << 3) + (lane & 7)) * APITCH
                                         + ((lane >> 3) & 1) * 16);
    const uint32_t pBaseHi = sb + AOFF_P + (wm * 16 + (lane & 15)) * PPITCH + (lane >> 4) * 16;
    const int vRow = ((lane >> 3) & 1) * 8 + (lane & 7);
    const uint32_t vCol = (uint32_t)(wn * 128 + (lane >> 4) * 16);

    const int rl0 = wm * 16 + (lane >> 2);

    float of[8][4];
    #pragma unroll
    for (int i = 0; i < 8; i++)
        #pragma unroll
        for (int j = 0; j < 4; j++) of[i][j] = 0.f;
    float m0 = -1e30f, m1 = -1e30f, l0 = 0.f, l1 = 0.f;

    const float sm_scale = 0.08838834764831843f;  // 1/sqrt(128)

    load_kv(0, 0); CP_COMMIT();
    load_kv(1, 1); CP_COMMIT();

    for (int t = 0; t < NKV; t++) {
        const int s = t & 1;
        CP_WAIT1();
        __syncthreads();

        const uint32_t sK  = sb + AOFF_STAGE + s * AKV_STAGE;
        const uint32_t sKl = sK + AQTILE;
        const uint32_t sV  = sK + 2 * AQTILE;
        const uint32_t sVl = sK + 3 * AQTILE;

        // ---- S = Q K^T ----
        float sf[4][4];
        #pragma unroll
        for (int nt = 0; nt < 4; nt++)
            #pragma unroll
            for (int j = 0; j < 4; j++) sf[nt][j] = 0.f;

        #pragma unroll
        for (int ks = 0; ks < 8; ks++) {
            uint32_t qh[4], ql[4], kh[4][2], kl[4][2];
            LDSM4(qh[0], qh[1], qh[2], qh[3], qBaseHi + ks * 32);
            LDSM4(ql[0], ql[1], ql[2], ql[3], qBaseHi + AQTILE + ks * 32);
            #pragma unroll
            for (int bt = 0; bt < 2; bt++) {
                uint32_t r0, r1, r2, r3;
                LDSM4(r0, r1, r2, r3, sK + kFragOff + bt * (16 * APITCH) + ks * 32);
                kh[bt * 2][0] = r0; kh[bt * 2][1] = r1;
                kh[bt * 2 + 1][0] = r2; kh[bt * 2 + 1][1] = r3;
                LDSM4(r0, r1, r2, r3, sKl + kFragOff + bt * (16 * APITCH) + ks * 32);
                kl[bt * 2][0] = r0; kl[bt * 2][1] = r1;
                kl[bt * 2 + 1][0] = r2; kl[bt * 2 + 1][1] = r3;
            }
            #pragma unroll
            for (int nt = 0; nt < 4; nt++) {
                MMA16816(sf[nt], qh, kh[nt]);
                MMA16816(sf[nt], qh, kl[nt]);
                MMA16816(sf[nt], ql, kh[nt]);
            }
        }

        // ---- online softmax ----
        #pragma unroll
        for (int nt = 0; nt < 4; nt++)
            #pragma unroll
            for (int j = 0; j < 4; j++) sf[nt][j] *= sm_scale;

        float mx0 = -1e30f, mx1 = -1e30f;
        #pragma unroll
        for (int nt = 0; nt < 4; nt++) {
            mx0 = fmaxf(mx0, fmaxf(sf[nt][0], sf[nt][1]));
            mx1 = fmaxf(mx1, fmaxf(sf[nt][2], sf[nt][3]));
        }
        mx0 = fmaxf(mx0, __shfl_xor_sync(0xffffffffu, mx0, 1));
        mx0 = fmaxf(mx0, __shfl_xor_sync(0xffffffffu, mx0, 2));
        mx1 = fmaxf(mx1, __shfl_xor_sync(0xffffffffu, mx1, 1));
        mx1 = fmaxf(mx1, __shfl_xor_sync(0xffffffffu, mx1, 2));
        if ((lane & 3) == 0) {
            rowmax[wn * 64 + rl0]     = mx0;
            rowmax[wn * 64 + rl0 + 8] = mx1;
        }
        __syncthreads();

        const float mn0 = fmaxf(m0, fmaxf(rowmax[rl0], rowmax[64 + rl0]));
        const float mn1 = fmaxf(m1, fmaxf(rowmax[rl0 + 8], rowmax[64 + rl0 + 8]));
        const float al0 = __expf(m0 - mn0);
        const float al1 = __expf(m1 - mn1);

        float sum0 = 0.f, sum1 = 0.f;
        #pragma unroll
        for (int nt = 0; nt < 4; nt++) {
            float p00 = __expf(sf[nt][0] - mn0);
            float p01 = __expf(sf[nt][1] - mn0);
            float p10 = __expf(sf[nt][2] - mn1);
            float p11 = __expf(sf[nt][3] - mn1);
            sum0 += p00 + p01;
            sum1 += p10 + p11;
            const uint32_t coff = (uint32_t)(wn * 64 + nt * 16 + (lane & 3) * 4);
            __nv_bfloat16 h00 = __float2bfloat16(p00), h01 = __float2bfloat16(p01);
            __nv_bfloat16 h10 = __float2bfloat16(p10), h11 = __float2bfloat16(p11);
            *(uint32_t*)(smem + AOFF_P + rl0 * PPITCH + coff) = packbf(p00, p01);
            *(uint32_t*)(smem + AOFF_P + (rl0 + 8) * PPITCH + coff) = packbf(p10, p11);
            *(uint32_t*)(smem + AOFF_PLO + rl0 * PPITCH + coff) =
                packbf(p00 - __bfloat162float(h00), p01 - __bfloat162float(h01));
            *(uint32_t*)(smem + AOFF_PLO + (rl0 + 8) * PPITCH + coff) =
                packbf(p10 - __bfloat162float(h10), p11 - __bfloat162float(h11));
        }
        sum0 += __shfl_xor_sync(0xffffffffu, sum0, 1);
        sum0 += __shfl_xor_sync(0xffffffffu, sum0, 2);
        sum1 += __shfl_xor_sync(0xffffffffu, sum1, 1);
        sum1 += __shfl_xor_sync(0xffffffffu, sum1, 2);
        if ((lane & 3) == 0) {
            rowsum[wn * 64 + rl0]     = sum0;
            rowsum[wn * 64 + rl0 + 8] = sum1;
        }
        __syncthreads();

        l0 = l0 * al0 + rowsum[rl0] + rowsum[64 + rl0];
        l1 = l1 * al1 + rowsum[rl0 + 8] + rowsum[64 + rl0 + 8];
        m0 = mn0; m1 = mn1;

        #pragma unroll
        for (int nt = 0; nt < 8; nt++) {
            of[nt][0] *= al0; of[nt][1] *= al0;
            of[nt][2] *= al1; of[nt][3] *= al1;
        }

        // ---- O += P V ----
        #pragma unroll
        for (int ks = 0; ks < 4; ks++) {
            uint32_t ph[4], pl[4];
            LDSM4(ph[0], ph[1], ph[2], ph[3], pBaseHi + ks * 32);
            LDSM4(pl[0], pl[1], pl[2], pl[3], pBaseHi + (64 * PPITCH) + ks * 32);
            const uint32_t vro = (uint32_t)((ks * 16 + vRow) * APITCH) + vCol;
            #pragma unroll
            for (int nt2 = 0; nt2 < 4; nt2++) {
                uint32_t r0, r1, r2, r3;
                uint32_t vh0[2], vh1[2], vl0[2], vl1[2];
                LDSM4T(r0, r1, r2, r3, sV + vro + nt2 * 32);
                vh0[0] = r0; vh0[1] = r1; vh1[0] = r2; vh1[1] = r3;
                LDSM4T(r0, r1, r2, r3, sVl + vro + nt2 * 32);
                vl0[0] = r0; vl0[1] = r1; vl1[0] = r2; vl1[1] = r3;
                MMA16816(of[nt2 * 2], ph, vh0);
                MMA16816(of[nt2 * 2], pl, vh0);
                MMA16816(of[nt2 * 2], ph, vl0);
                MMA16816(of[nt2 * 2 + 1], ph, vh1);
                MMA16816(of[nt2 * 2 + 1], pl, vh1);
                MMA16816(of[nt2 * 2 + 1], ph, vl1);
            }
        }

        __syncthreads();   // all reads of stage s / P done before reuse
        if (t + 2 < NKV) { load_kv(t + 2, s); CP_COMMIT(); }
    }

    // ---- epilogue: O/l -> bf16 hi/lo at [b, s, d] ----
    const int b = bh >> 4;
    const int h = bh & 15;
    const float inv0 = 1.0f / l0;
    const float inv1 = 1.0f / l1;
    const int s0 = q0 + rl0;
    #pragma unroll
    for (int nt = 0; nt < 8; nt++) {
        const int d = h * 128 + wn * 64 + nt * 8 + (lane & 3) * 2;
        size_t idx0 = ((size_t)(b * SS + s0)) * DD + d;
        size_t idx1 = idx0 + (size_t)8 * DD;
        float a0 = of[nt][0] * inv0, a1 = of[nt][1] * inv0;
        float a2 = of[nt][2] * inv1, a3 = of[nt][3] * inv1;
        __nv_bfloat16 h0 = __float2bfloat16(a0), h1 = __float2bfloat16(a1);
        __nv_bfloat16 h2 = __float2bfloat16(a2), h3 = __float2bfloat16(a3);
        *(uint32_t*)(Ahi + idx0) = packbf(a0, a1);
        *(uint32_t*)(Ahi + idx1) = packbf(a2, a3);
        *(uint32_t*)(Alo + idx0) = packbf(a0 - __bfloat162float(h0), a1 - __bfloat162float(h1));
        *(uint32_t*)(Alo + idx1) = packbf(a2 - __bfloat162float(h2), a3 - __bfloat162float(h3));
    }
}

// ---------------------------------------------------------------------------
extern "C" void kernel_launch(void* const* d_in, const int* in_sizes, int n_in,
                              void* d_out, int out_size)
{
    const float* x  = (const float*)d_in[0];
    const float* Wq = (const float*)d_in[1];
    const float* Wk = (const float*)d_in[2];
    const float* Wv = (const float*)d_in[3];
    const float* Wo = (const float*)d_in[4];

    __nv_bfloat16 *xhi, *xlo, *whi, *wlo;
    __nv_bfloat16 *qhi, *qlo, *khi, *klo, *vhi, *vlo, *ahi, *alo;
    cudaGetSymbolAddress((void**)&xhi, g_xhi);
    cudaGetSymbolAddress((void**)&xlo, g_xlo);
    cudaGetSymbolAddress((void**)&whi, g_whi);
    cudaGetSymbolAddress((void**)&wlo, g_wlo);
    cudaGetSymbolAddress((void**)&qhi, g_qhi);
    cudaGetSymbolAddress((void**)&qlo, g_qlo);
    cudaGetSymbolAddress((void**)&khi, g_khi);
    cudaGetSymbolAddress((void**)&klo, g_klo);
    cudaGetSymbolAddress((void**)&vhi, g_vhi);
    cudaGetSymbolAddress((void**)&vlo, g_vlo);
    cudaGetSymbolAddress((void**)&ahi, g_ahi);
    cudaGetSymbolAddress((void**)&alo, g_alo);

    cudaFuncSetAttribute(gemm_hmma, cudaFuncAttributeMaxDynamicSharedMemorySize,
                         GSMEM_TOTAL);
    cudaFuncSetAttribute(attn_hmma, cudaFuncAttributeMaxDynamicSharedMemorySize,
                         ATT_SMEM);

    const int xn4 = (int)((size_t)MTOT * DD / 4);   // 2M
    const int wn4 = (int)((size_t)DD * DD / 4);     // 1M

    // One fused split launch for x + 4 weights
    split_all_kernel<<<dim3((xn4 + 255) / 256, 5), 256>>>(
        x, Wq, Wk, Wv, Wo, xhi, xlo, whi, wlo, xn4, wn4);

    // Merged Q/K/V projections: gridDim.z = 3
    dim3 gqkv(DD / 128, MTOT / 128, 3);
    gemm_hmma<<<gqkv, 256, GSMEM_TOTAL>>>(xhi, xlo, whi, wlo, nullptr,
                                          qhi, qlo, khi, klo, vhi, vlo, 1);

    attn_hmma<<<dim3(SS / 64, Bb * HH), 256, ATT_SMEM>>>(
        qhi, qlo, khi, klo, vhi, vlo, ahi, alo);

    // Output projection: Wo is weight slice 3
    dim3 go(DD / 128, MTOT / 128, 1);
    gemm_hmma<<<go, 256, GSMEM_TOTAL>>>(ahi, alo,
                                        whi + (size_t)3 * DD * DD,
                                        wlo + (size_t)3 * DD * DD,
                                        (float*)d_out,
                                        nullptr, nullptr, nullptr, nullptr,
                                        nullptr, nullptr, 0);
}

// round 6
// speedup vs baseline: 3.1270x; 1.0262x over previous
#include <cuda_runtime.h>
#include <cuda_bf16.h>
#include <stdint.h>
#include <math.h>

// Problem constants
#define Bb   2
#define SS   2048
#define DD   2048
#define HH   16
#define HD   128
#define MTOT 4096   // Bb*SS
#define KK   2048

// ---------------------------------------------------------------------------
// Scratch (device globals: allocation-free rule)
// ---------------------------------------------------------------------------
__device__ __nv_bfloat16 g_xhi[(size_t)MTOT * DD];
__device__ __nv_bfloat16 g_xlo[(size_t)MTOT * DD];
__device__ __nv_bfloat16 g_whi[(size_t)4 * DD * DD];  // Wq,Wk,Wv,Wo
__device__ __nv_bfloat16 g_wlo[(size_t)4 * DD * DD];
__device__ __nv_bfloat16 g_qhi[(size_t)Bb * HH * SS * HD];  // [b,h,s,hd]
__device__ __nv_bfloat16 g_qlo[(size_t)Bb * HH * SS * HD];
__device__ __nv_bfloat16 g_khi[(size_t)Bb * HH * SS * HD];
__device__ __nv_bfloat16 g_klo[(size_t)Bb * HH * SS * HD];
__device__ __nv_bfloat16 g_vhi[(size_t)Bb * HH * SS * HD];
__device__ __nv_bfloat16 g_vlo[(size_t)Bb * HH * SS * HD];
__device__ __nv_bfloat16 g_ahi[(size_t)MTOT * DD];          // attn out [b,s,d]
__device__ __nv_bfloat16 g_alo[(size_t)MTOT * DD];

// ---------------------------------------------------------------------------
// PTX helpers (family-safe: sm_80-class instructions only)
// ---------------------------------------------------------------------------
__device__ __forceinline__ uint32_t smem_to_u32(const void* p) {
    uint32_t a;
    asm("{ .reg .u64 t; cvta.to.shared.u64 t, %1; cvt.u32.u64 %0, t; }"
        : "=r"(a) : "l"(p));
    return a;
}

__device__ __forceinline__ void cp_async16(uint32_t saddr, const void* gaddr) {
    asm volatile("cp.async.cg.shared.global [%0], [%1], 16;"
                 :: "r"(saddr), "l"(gaddr) : "memory");
}
#define CP_COMMIT() asm volatile("cp.async.commit_group;" ::: "memory")
#define CP_WAIT1()  asm volatile("cp.async.wait_group 1;" ::: "memory")
#define CP_WAIT2()  asm volatile("cp.async.wait_group 2;" ::: "memory")

#define LDSM4(r0, r1, r2, r3, addr) \
    asm volatile("ldmatrix.sync.aligned.m8n8.x4.shared.b16 {%0,%1,%2,%3}, [%4];" \
                 : "=r"(r0), "=r"(r1), "=r"(r2), "=r"(r3) : "r"(addr))

#define LDSM4T(r0, r1, r2, r3, addr) \
    asm volatile("ldmatrix.sync.aligned.m8n8.x4.trans.shared.b16 {%0,%1,%2,%3}, [%4];" \
                 : "=r"(r0), "=r"(r1), "=r"(r2), "=r"(r3) : "r"(addr))

#define MMA16816(d, a, b) \
    asm volatile("mma.sync.aligned.m16n8k16.row.col.f32.bf16.bf16.f32 " \
                 "{%0,%1,%2,%3}, {%4,%5,%6,%7}, {%8,%9}, {%0,%1,%2,%3};" \
                 : "+f"((d)[0]), "+f"((d)[1]), "+f"((d)[2]), "+f"((d)[3]) \
                 : "r"((a)[0]), "r"((a)[1]), "r"((a)[2]), "r"((a)[3]), \
                   "r"((b)[0]), "r"((b)[1]))

__device__ __forceinline__ uint32_t packbf(float x, float y) {
    __nv_bfloat162 t = __floats2bfloat162_rn(x, y);
    return *(uint32_t*)&t;
}

// ---------------------------------------------------------------------------
// Fused split: one launch handles x and all 4 weights.
// blockIdx.y: 0 -> x, 1..4 -> W[y-1].
// ---------------------------------------------------------------------------
__global__ __launch_bounds__(256) void split_all_kernel(
    const float* __restrict__ x,  const float* __restrict__ Wq,
    const float* __restrict__ Wk, const float* __restrict__ Wv,
    const float* __restrict__ Wo,
    __nv_bfloat16* __restrict__ xhi, __nv_bfloat16* __restrict__ xlo,
    __nv_bfloat16* __restrict__ whi, __nv_bfloat16* __restrict__ wlo,
    int xn4, int wn4)
{
    const int y = blockIdx.y;
    const float* in;
    __nv_bfloat16 *hi, *lo;
    int n4;
    if (y == 0) { in = x; hi = xhi; lo = xlo; n4 = xn4; }
    else {
        const float* ws[4] = {Wq, Wk, Wv, Wo};
        in = ws[y - 1];
        const size_t off = (size_t)(y - 1) * DD * DD;
        hi = whi + off; lo = wlo + off; n4 = wn4;
    }
    int i = blockIdx.x * blockDim.x + threadIdx.x;
    if (i >= n4) return;
    float4 v = ((const float4*)in)[i];
    __nv_bfloat16 h0 = __float2bfloat16(v.x);
    __nv_bfloat16 h1 = __float2bfloat16(v.y);
    __nv_bfloat16 h2 = __float2bfloat16(v.z);
    __nv_bfloat16 h3 = __float2bfloat16(v.w);
    ((__nv_bfloat162*)hi)[2 * i + 0] = __halves2bfloat162(h0, h1);
    ((__nv_bfloat162*)hi)[2 * i + 1] = __halves2bfloat162(h2, h3);
    ((__nv_bfloat162*)lo)[2 * i + 0] = __halves2bfloat162(
        __float2bfloat16(v.x - __bfloat162float(h0)),
        __float2bfloat16(v.y - __bfloat162float(h1)));
    ((__nv_bfloat162*)lo)[2 * i + 1] = __halves2bfloat162(
        __float2bfloat16(v.z - __bfloat162float(h2)),
        __float2bfloat16(v.w - __bfloat162float(h3)));
}

// ---------------------------------------------------------------------------
// HMMA GEMM, 512 threads / 16 warps, warp tile 32x32 (4 warps per SMSP).
// CTA tile 128x128, BK=32, 4-stage cp.async pipeline, one barrier per chunk.
// qkv==1: gridDim.z selects weight slice + output (Q/K/V), bf16 hi/lo out.
// ---------------------------------------------------------------------------
#define TPITCHB  80            // bytes per smem row
#define TILEB    10240         // 128 * 80
#define STAGEB   40960
#define NSTAGE   4
#define GSMEM_TOTAL (NSTAGE * STAGEB)
#define NCHUNK   (KK / 32)

__global__ __launch_bounds__(512, 1) void gemm_hmma(
    const __nv_bfloat16* __restrict__ Xhi, const __nv_bfloat16* __restrict__ Xlo,
    const __nv_bfloat16* __restrict__ WhiBase, const __nv_bfloat16* __restrict__ WloBase,
    float* __restrict__ Yf,
    __nv_bfloat16* __restrict__ Y0hi, __nv_bfloat16* __restrict__ Y0lo,
    __nv_bfloat16* __restrict__ Y1hi, __nv_bfloat16* __restrict__ Y1lo,
    __nv_bfloat16* __restrict__ Y2hi, __nv_bfloat16* __restrict__ Y2lo,
    int qkv)
{
    extern __shared__ char smem[];
    const uint32_t sb = smem_to_u32(smem);

    const int tid  = threadIdx.x;
    const int wid  = tid >> 5;
    const int lane = tid & 31;
    const int wm   = wid >> 2;    // 0..3  (32-row band)
    const int wn   = wid & 3;     // 0..3  (32-col band)
    const int m0   = blockIdx.y * 128;
    const int n0   = blockIdx.x * 128;
    const int z    = blockIdx.z;

    const __nv_bfloat16* Whi = WhiBase + (size_t)z * DD * DD;
    const __nv_bfloat16* Wlo = WloBase + (size_t)z * DD * DD;

    // loader: 4 groups of 128 threads, one tile each (Ahi/Alo/Bhi/Blo)
    const int ltile = tid >> 7;
    const int lwi   = tid & 127;
    const __nv_bfloat16* gbase =
        (ltile == 0) ? Xhi : (ltile == 1) ? Xlo : (ltile == 2) ? Whi : Wlo;
    const int rowoff = (ltile < 2) ? m0 : n0;
    const uint32_t stile = sb + ltile * TILEB;

    auto load_stage = [&](int chunk, int s) {
        const int k0 = chunk * 32;
        const uint32_t sstage = stile + s * STAGEB;
        #pragma unroll
        for (int i = 0; i < 4; i++) {
            int idx = lwi + i * 128;
            int row = idx >> 2;
            int c   = idx & 3;
            cp_async16(sstage + (uint32_t)(row * TPITCHB + c * 16),
                       gbase + (size_t)(rowoff + row) * KK + k0 + c * 8);
        }
    };

    const uint32_t aoff = (uint32_t)((wm * 32 + (lane & 15)) * TPITCHB + (lane >> 4) * 16);
    const uint32_t boff = (uint32_t)((wn * 32 + ((lane >> 4) << 3) + (lane & 7)) * TPITCHB
                                     + ((lane >> 3) & 1) * 16);

    float acc[2][4][4];
    #pragma unroll
    for (int mt = 0; mt < 2; mt++)
        #pragma unroll
        for (int nt = 0; nt < 4; nt++)
            #pragma unroll
            for (int r = 0; r < 4; r++) acc[mt][nt][r] = 0.f;

    load_stage(0, 0); CP_COMMIT();
    load_stage(1, 1); CP_COMMIT();
    load_stage(2, 2); CP_COMMIT();

    for (int t = 0; t < NCHUNK; t++) {
        const int s = t & 3;
        CP_WAIT2();            // stage t resident
        __syncthreads();       // visible to all; reads of slot (t+3)&3 complete

        if (t + 3 < NCHUNK) load_stage(t + 3, (t + 3) & 3);
        CP_COMMIT();

        const uint32_t stA  = sb + s * STAGEB;
        const uint32_t stAl = stA + TILEB;
        const uint32_t stB  = stA + 2 * TILEB;
        const uint32_t stBl = stA + 3 * TILEB;

        #pragma unroll
        for (int ks = 0; ks < 2; ks++) {
            uint32_t ah[2][4], al[2][4], bh[4][2], bl[4][2];
            #pragma unroll
            for (int mt = 0; mt < 2; mt++) {
                LDSM4(ah[mt][0], ah[mt][1], ah[mt][2], ah[mt][3],
                      stA  + aoff + mt * (16 * TPITCHB) + ks * 32);
                LDSM4(al[mt][0], al[mt][1], al[mt][2], al[mt][3],
                      stAl + aoff + mt * (16 * TPITCHB) + ks * 32);
            }
            #pragma unroll
            for (int bt = 0; bt < 2; bt++) {
                uint32_t r0, r1, r2, r3;
                LDSM4(r0, r1, r2, r3, stB + boff + bt * (16 * TPITCHB) + ks * 32);
                bh[bt * 2][0] = r0; bh[bt * 2][1] = r1;
                bh[bt * 2 + 1][0] = r2; bh[bt * 2 + 1][1] = r3;
                LDSM4(r0, r1, r2, r3, stBl + boff + bt * (16 * TPITCHB) + ks * 32);
                bl[bt * 2][0] = r0; bl[bt * 2][1] = r1;
                bl[bt * 2 + 1][0] = r2; bl[bt * 2 + 1][1] = r3;
            }
            #pragma unroll
            for (int mt = 0; mt < 2; mt++)
                #pragma unroll
                for (int nt = 0; nt < 4; nt++) {
                    MMA16816(acc[mt][nt], ah[mt], bh[nt]);
                    MMA16816(acc[mt][nt], ah[mt], bl[nt]);
                    MMA16816(acc[mt][nt], al[mt], bh[nt]);
                }
        }
    }

    // ---- epilogue ----
    __nv_bfloat16* Yhi = (z == 0) ? Y0hi : (z == 1) ? Y1hi : Y2hi;
    __nv_bfloat16* Ylo = (z == 0) ? Y0lo : (z == 1) ? Y1lo : Y2lo;
    #pragma unroll
    for (int mt = 0; mt < 2; mt++) {
        const int mrow = m0 + wm * 32 + mt * 16 + (lane >> 2);
        #pragma unroll
        for (int nt = 0; nt < 4; nt++) {
            const int ncl = wn * 32 + nt * 8 + (lane & 3) * 2;
            if (qkv) {
                const int b = mrow >> 11;
                const int srow = mrow & 2047;
                const int h = n0 >> 7;
                size_t idx0 = (((size_t)(b * HH + h) * SS) + srow) * HD + ncl;
                size_t idx1 = idx0 + (size_t)8 * HD;
                float a0 = acc[mt][nt][0], a1 = acc[mt][nt][1];
                float a2 = acc[mt][nt][2], a3 = acc[mt][nt][3];
                __nv_bfloat16 h0 = __float2bfloat16(a0), h1 = __float2bfloat16(a1);
                __nv_bfloat16 h2 = __float2bfloat16(a2), h3 = __float2bfloat16(a3);
                *(uint32_t*)(Yhi + idx0) = packbf(a0, a1);
                *(uint32_t*)(Yhi + idx1) = packbf(a2, a3);
                *(uint32_t*)(Ylo + idx0) =
                    packbf(a0 - __bfloat162float(h0), a1 - __bfloat162float(h1));
                *(uint32_t*)(Ylo + idx1) =
                    packbf(a2 - __bfloat162float(h2), a3 - __bfloat162float(h3));
            } else {
                float* basep = Yf + (size_t)mrow * DD + n0 + ncl;
                *(float2*)basep = make_float2(acc[mt][nt][0], acc[mt][nt][1]);
                *(float2*)(basep + (size_t)8 * DD) = make_float2(acc[mt][nt][2], acc[mt][nt][3]);
            }
        }
    }
}

// ---------------------------------------------------------------------------
// HMMA flash attention (unchanged from round 5).
// ---------------------------------------------------------------------------
#define APITCH   272
#define PPITCH   144
#define AQTILE   (64 * APITCH)      // 17408
#define AKV_STAGE (4 * AQTILE)      // 69632
#define AOFF_Q    0
#define AOFF_STAGE (2 * AQTILE)
#define AOFF_P    (AOFF_STAGE + 2 * AKV_STAGE)
#define AOFF_PLO  (AOFF_P + 64 * PPITCH)
#define AOFF_STAT (AOFF_PLO + 64 * PPITCH)
#define ATT_SMEM  (AOFF_STAT + 1024)
#define NKV       (SS / 64)

__global__ __launch_bounds__(256, 1) void attn_hmma(
    const __nv_bfloat16* __restrict__ Qhi_g, const __nv_bfloat16* __restrict__ Qlo_g,
    const __nv_bfloat16* __restrict__ Khi_g, const __nv_bfloat16* __restrict__ Klo_g,
    const __nv_bfloat16* __restrict__ Vhi_g, const __nv_bfloat16* __restrict__ Vlo_g,
    __nv_bfloat16* __restrict__ Ahi, __nv_bfloat16* __restrict__ Alo)
{
    extern __shared__ char smem[];
    const uint32_t sb = smem_to_u32(smem);
    float* rowmax = (float*)(smem + AOFF_STAT);          // [2][64]
    float* rowsum = rowmax + 128;                        // [2][64]

    const int tid  = threadIdx.x;
    const int wid  = tid >> 5;
    const int lane = tid & 31;
    const int wm   = wid >> 1;   // 0..3
    const int wn   = wid & 1;    // 0..1
    const int q0   = blockIdx.x * 64;
    const int bh   = blockIdx.y;
    const size_t bhoff = (size_t)bh * SS * HD;

    {
        const __nv_bfloat16* qh = Qhi_g + bhoff + (size_t)q0 * HD;
        const __nv_bfloat16* ql = Qlo_g + bhoff + (size_t)q0 * HD;
        for (int i = tid; i < 64 * 16; i += 256) {
            int r = i >> 4, c = i & 15;
            *(uint4*)(smem + AOFF_Q + r * APITCH + c * 16) =
                *(const uint4*)(qh + (size_t)r * HD + c * 8);
            *(uint4*)(smem + AOFF_Q + AQTILE + r * APITCH + c * 16) =
                *(const uint4*)(ql + (size_t)r * HD + c * 8);
        }
    }

    const __nv_bfloat16* kvbase[4] = {Khi_g + bhoff, Klo_g + bhoff,
                                      Vhi_g + bhoff, Vlo_g + bhoff};
    auto load_kv = [&](int chunk, int s) {
        const uint32_t sstage = sb + AOFF_STAGE + s * AKV_STAGE;
        #pragma unroll
        for (int t = 0; t < 16; t++) {
            int tile = t >> 2;
            int r = (16 * t + (tid >> 4)) & 63;
            int c = tid & 15;
            cp_async16(sstage + tile * AQTILE + r * APITCH + c * 16,
                       kvbase[tile] + (size_t)(chunk * 64 + r) * HD + c * 8);
        }
    };

    const uint32_t qBaseHi = sb + AOFF_Q + (wm * 16 + (lane & 15)) * APITCH + (lane >> 4) * 16;
    const uint32_t kFragOff = (uint32_t)((wn * 32 + ((lane >> 4) << 3) + (lane & 7)) * APITCH
                                         + ((lane >> 3) & 1) * 16);
    const uint32_t pBaseHi = sb + AOFF_P + (wm * 16 + (lane & 15)) * PPITCH + (lane >> 4) * 16;
    const int vRow = ((lane >> 3) & 1) * 8 + (lane & 7);
    const uint32_t vCol = (uint32_t)(wn * 128 + (lane >> 4) * 16);

    const int rl0 = wm * 16 + (lane >> 2);

    float of[8][4];
    #pragma unroll
    for (int i = 0; i < 8; i++)
        #pragma unroll
        for (int j = 0; j < 4; j++) of[i][j] = 0.f;
    float m0 = -1e30f, m1 = -1e30f, l0 = 0.f, l1 = 0.f;

    const float sm_scale = 0.08838834764831843f;  // 1/sqrt(128)

    load_kv(0, 0); CP_COMMIT();
    load_kv(1, 1); CP_COMMIT();

    for (int t = 0; t < NKV; t++) {
        const int s = t & 1;
        CP_WAIT1();
        __syncthreads();

        const uint32_t sK  = sb + AOFF_STAGE + s * AKV_STAGE;
        const uint32_t sKl = sK + AQTILE;
        const uint32_t sV  = sK + 2 * AQTILE;
        const uint32_t sVl = sK + 3 * AQTILE;

        float sf[4][4];
        #pragma unroll
        for (int nt = 0; nt < 4; nt++)
            #pragma unroll
            for (int j = 0; j < 4; j++) sf[nt][j] = 0.f;

        #pragma unroll
        for (int ks = 0; ks < 8; ks++) {
            uint32_t qh[4], ql[4], kh[4][2], kl[4][2];
            LDSM4(qh[0], qh[1], qh[2], qh[3], qBaseHi + ks * 32);
            LDSM4(ql[0], ql[1], ql[2], ql[3], qBaseHi + AQTILE + ks * 32);
            #pragma unroll
            for (int bt = 0; bt < 2; bt++) {
                uint32_t r0, r1, r2, r3;
                LDSM4(r0, r1, r2, r3, sK + kFragOff + bt * (16 * APITCH) + ks * 32);
                kh[bt * 2][0] = r0; kh[bt * 2][1] = r1;
                kh[bt * 2 + 1][0] = r2; kh[bt * 2 + 1][1] = r3;
                LDSM4(r0, r1, r2, r3, sKl + kFragOff + bt * (16 * APITCH) + ks * 32);
                kl[bt * 2][0] = r0; kl[bt * 2][1] = r1;
                kl[bt * 2 + 1][0] = r2; kl[bt * 2 + 1][1] = r3;
            }
            #pragma unroll
            for (int nt = 0; nt < 4; nt++) {
                MMA16816(sf[nt], qh, kh[nt]);
                MMA16816(sf[nt], qh, kl[nt]);
                MMA16816(sf[nt], ql, kh[nt]);
            }
        }

        #pragma unroll
        for (int nt = 0; nt < 4; nt++)
            #pragma unroll
            for (int j = 0; j < 4; j++) sf[nt][j] *= sm_scale;

        float mx0 = -1e30f, mx1 = -1e30f;
        #pragma unroll
        for (int nt = 0; nt < 4; nt++) {
            mx0 = fmaxf(mx0, fmaxf(sf[nt][0], sf[nt][1]));
            mx1 = fmaxf(mx1, fmaxf(sf[nt][2], sf[nt][3]));
        }
        mx0 = fmaxf(mx0, __shfl_xor_sync(0xffffffffu, mx0, 1));
        mx0 = fmaxf(mx0, __shfl_xor_sync(0xffffffffu, mx0, 2));
        mx1 = fmaxf(mx1, __shfl_xor_sync(0xffffffffu, mx1, 1));
        mx1 = fmaxf(mx1, __shfl_xor_sync(0xffffffffu, mx1, 2));
        if ((lane & 3) == 0) {
            rowmax[wn * 64 + rl0]     = mx0;
            rowmax[wn * 64 + rl0 + 8] = mx1;
        }
        __syncthreads();

        const float mn0 = fmaxf(m0, fmaxf(rowmax[rl0], rowmax[64 + rl0]));
        const float mn1 = fmaxf(m1, fmaxf(rowmax[rl0 + 8], rowmax[64 + rl0 + 8]));
        const float al0 = __expf(m0 - mn0);
        const float al1 = __expf(m1 - mn1);

        float sum0 = 0.f, sum1 = 0.f;
        #pragma unroll
        for (int nt = 0; nt < 4; nt++) {
            float p00 = __expf(sf[nt][0] - mn0);
            float p01 = __expf(sf[nt][1] - mn0);
            float p10 = __expf(sf[nt][2] - mn1);
            float p11 = __expf(sf[nt][3] - mn1);
            sum0 += p00 + p01;
            sum1 += p10 + p11;
            const uint32_t coff = (uint32_t)(wn * 64 + nt * 16 + (lane & 3) * 4);
            __nv_bfloat16 h00 = __float2bfloat16(p00), h01 = __float2bfloat16(p01);
            __nv_bfloat16 h10 = __float2bfloat16(p10), h11 = __float2bfloat16(p11);
            *(uint32_t*)(smem + AOFF_P + rl0 * PPITCH + coff) = packbf(p00, p01);
            *(uint32_t*)(smem + AOFF_P + (rl0 + 8) * PPITCH + coff) = packbf(p10, p11);
            *(uint32_t*)(smem + AOFF_PLO + rl0 * PPITCH + coff) =
                packbf(p00 - __bfloat162float(h00), p01 - __bfloat162float(h01));
            *(uint32_t*)(smem + AOFF_PLO + (rl0 + 8) * PPITCH + coff) =
                packbf(p10 - __bfloat162float(h10), p11 - __bfloat162float(h11));
        }
        sum0 += __shfl_xor_sync(0xffffffffu, sum0, 1);
        sum0 += __shfl_xor_sync(0xffffffffu, sum0, 2);
        sum1 += __shfl_xor_sync(0xffffffffu, sum1, 1);
        sum1 += __shfl_xor_sync(0xffffffffu, sum1, 2);
        if ((lane & 3) == 0) {
            rowsum[wn * 64 + rl0]     = sum0;
            rowsum[wn * 64 + rl0 + 8] = sum1;
        }
        __syncthreads();

        l0 = l0 * al0 + rowsum[rl0] + rowsum[64 + rl0];
        l1 = l1 * al1 + rowsum[rl0 + 8] + rowsum[64 + rl0 + 8];
        m0 = mn0; m1 = mn1;

        #pragma unroll
        for (int nt = 0; nt < 8; nt++) {
            of[nt][0] *= al0; of[nt][1] *= al0;
            of[nt][2] *= al1; of[nt][3] *= al1;
        }

        #pragma unroll
        for (int ks = 0; ks < 4; ks++) {
            uint32_t ph[4], pl[4];
            LDSM4(ph[0], ph[1], ph[2], ph[3], pBaseHi + ks * 32);
            LDSM4(pl[0], pl[1], pl[2], pl[3], pBaseHi + (64 * PPITCH) + ks * 32);
            const uint32_t vro = (uint32_t)((ks * 16 + vRow) * APITCH) + vCol;
            #pragma unroll
            for (int nt2 = 0; nt2 < 4; nt2++) {
                uint32_t r0, r1, r2, r3;
                uint32_t vh0[2], vh1[2], vl0[2], vl1[2];
                LDSM4T(r0, r1, r2, r3, sV + vro + nt2 * 32);
                vh0[0] = r0; vh0[1] = r1; vh1[0] = r2; vh1[1] = r3;
                LDSM4T(r0, r1, r2, r3, sVl + vro + nt2 * 32);
                vl0[0] = r0; vl0[1] = r1; vl1[0] = r2; vl1[1] = r3;
                MMA16816(of[nt2 * 2], ph, vh0);
                MMA16816(of[nt2 * 2], pl, vh0);
                MMA16816(of[nt2 * 2], ph, vl0);
                MMA16816(of[nt2 * 2 + 1], ph, vh1);
                MMA16816(of[nt2 * 2 + 1], pl, vh1);
                MMA16816(of[nt2 * 2 + 1], ph, vl1);
            }
        }

        __syncthreads();
        if (t + 2 < NKV) { load_kv(t + 2, s); CP_COMMIT(); }
    }

    const int b = bh >> 4;
    const int h = bh & 15;
    const float inv0 = 1.0f / l0;
    const float inv1 = 1.0f / l1;
    const int s0 = q0 + rl0;
    #pragma unroll
    for (int nt = 0; nt < 8; nt++) {
        const int d = h * 128 + wn * 64 + nt * 8 + (lane & 3) * 2;
        size_t idx0 = ((size_t)(b * SS + s0)) * DD + d;
        size_t idx1 = idx0 + (size_t)8 * DD;
        float a0 = of[nt][0] * inv0, a1 = of[nt][1] * inv0;
        float a2 = of[nt][2] * inv1, a3 = of[nt][3] * inv1;
        __nv_bfloat16 h0 = __float2bfloat16(a0), h1 = __float2bfloat16(a1);
        __nv_bfloat16 h2 = __float2bfloat16(a2), h3 = __float2bfloat16(a3);
        *(uint32_t*)(Ahi + idx0) = packbf(a0, a1);
        *(uint32_t*)(Ahi + idx1) = packbf(a2, a3);
        *(uint32_t*)(Alo + idx0) = packbf(a0 - __bfloat162float(h0), a1 - __bfloat162float(h1));
        *(uint32_t*)(Alo + idx1) = packbf(a2 - __bfloat162float(h2), a3 - __bfloat162float(h3));
    }
}

// ---------------------------------------------------------------------------
extern "C" void kernel_launch(void* const* d_in, const int* in_sizes, int n_in,
                              void* d_out, int out_size)
{
    const float* x  = (const float*)d_in[0];
    const float* Wq = (const float*)d_in[1];
    const float* Wk = (const float*)d_in[2];
    const float* Wv = (const float*)d_in[3];
    const float* Wo = (const float*)d_in[4];

    __nv_bfloat16 *xhi, *xlo, *whi, *wlo;
    __nv_bfloat16 *qhi, *qlo, *khi, *klo, *vhi, *vlo, *ahi, *alo;
    cudaGetSymbolAddress((void**)&xhi, g_xhi);
    cudaGetSymbolAddress((void**)&xlo, g_xlo);
    cudaGetSymbolAddress((void**)&whi, g_whi);
    cudaGetSymbolAddress((void**)&wlo, g_wlo);
    cudaGetSymbolAddress((void**)&qhi, g_qhi);
    cudaGetSymbolAddress((void**)&qlo, g_qlo);
    cudaGetSymbolAddress((void**)&khi, g_khi);
    cudaGetSymbolAddress((void**)&klo, g_klo);
    cudaGetSymbolAddress((void**)&vhi, g_vhi);
    cudaGetSymbolAddress((void**)&vlo, g_vlo);
    cudaGetSymbolAddress((void**)&ahi, g_ahi);
    cudaGetSymbolAddress((void**)&alo, g_alo);

    cudaFuncSetAttribute(gemm_hmma, cudaFuncAttributeMaxDynamicSharedMemorySize,
                         GSMEM_TOTAL);
    cudaFuncSetAttribute(attn_hmma, cudaFuncAttributeMaxDynamicSharedMemorySize,
                         ATT_SMEM);

    const int xn4 = (int)((size_t)MTOT * DD / 4);   // 2M
    const int wn4 = (int)((size_t)DD * DD / 4);     // 1M

    split_all_kernel<<<dim3((xn4 + 255) / 256, 5), 256>>>(
        x, Wq, Wk, Wv, Wo, xhi, xlo, whi, wlo, xn4, wn4);

    dim3 gqkv(DD / 128, MTOT / 128, 3);
    gemm_hmma<<<gqkv, 512, GSMEM_TOTAL>>>(xhi, xlo, whi, wlo, nullptr,
                                          qhi, qlo, khi, klo, vhi, vlo, 1);

    attn_hmma<<<dim3(SS / 64, Bb * HH), 256, ATT_SMEM>>>(
        qhi, qlo, khi, klo, vhi, vlo, ahi, alo);

    dim3 go(DD / 128, MTOT / 128, 1);
    gemm_hmma<<<go, 512, GSMEM_TOTAL>>>(ahi, alo,
                                        whi + (size_t)3 * DD * DD,
                                        wlo + (size_t)3 * DD * DD,
                                        (float*)d_out,
                                        nullptr, nullptr, nullptr, nullptr,
                                        nullptr, nullptr, 0);
}